// round 3
// baseline (speedup 1.0000x reference)
#include <cuda_runtime.h>
#include <cuda_bf16.h>
#include <math.h>

// ---------------- problem constants ----------------
constexpr int Bb = 4;
constexpr int Ss = 4096;
constexpr int Ee = 1024;
constexpr int Hh = 16;
constexpr int Dd = 64;
constexpr int Mtot = Bb * Ss;          // 16384 projection rows
constexpr int HRows = Mtot * Hh;       // 262144 head-rows (64 wide)

// ---------------- scratch (device globals; no allocation allowed) ----------------
// NOTE: these symbols are ONLY referenced from device code (via templates).
// Passing them as host-side kernel arguments is illegal and was the Round1/2 bug.
__device__ __align__(16) float g_QH[(size_t)Mtot * Ee];
__device__ __align__(16) float g_KH[(size_t)Mtot * Ee];
__device__ __align__(16) float g_VH[(size_t)Mtot * Ee];
__device__ __align__(16) float g_ctx[Bb * Hh * Dd * Dd];
__device__ __align__(16) float g_kcum[Bb * Hh * Dd];
__device__ __align__(16) float g_khm[Ee];     // exact masked-k-row softmax (per head)
__device__ unsigned char g_qm[Mtot];
__device__ unsigned char g_km[Mtot];

// =====================================================================
// Mask normalization: harness may store bool masks as 1-byte (bool/int8),
// int32 (0/1) or float32 (0.0/1.0). Detect by scanning the first n/4
// words: byte-packed random 0/1 data yields words outside
// {0, 1, 0x3F800000} with overwhelming probability.
// QM=true -> write g_qm, else g_km.
// =====================================================================
template<bool QM>
__global__ void norm_mask_kernel(const unsigned char* __restrict__ src, int n)
{
    unsigned char* dst = QM ? g_qm : g_km;
    __shared__ int vote_u8, any_nz;
    if (threadIdx.x == 0) { vote_u8 = 0; any_nz = 0; }
    __syncthreads();

    const unsigned int* w = (const unsigned int*)src;
    const int nw = n >> 2;
    int l_u8 = 0, l_nz = 0;
    for (int i = threadIdx.x; i < nw; i += blockDim.x) {
        unsigned int vv = w[i];
        if (vv != 0u) l_nz = 1;
        if (vv != 0u && vv != 1u && vv != 0x3F800000u) l_u8 = 1;
    }
    if (l_u8) vote_u8 = 1;
    if (l_nz) any_nz = 1;
    __syncthreads();

    if (!any_nz) {
        for (int i = threadIdx.x; i < n; i += blockDim.x) dst[i] = 0;
    } else if (vote_u8) {
        for (int i = threadIdx.x; i < n; i += blockDim.x) dst[i] = src[i] ? 1 : 0;
    } else {
        for (int i = threadIdx.x; i < n; i += blockDim.x) dst[i] = w[i] ? 1 : 0;
    }
}

// =====================================================================
// SGEMM: C[m,n] = (sum_e A_eff[m,e] * W[n,e] + bias[n]) * outmask
//   A: MxK row-major, W: NxK row-major (C = A @ W^T), M=16384, N=K=1024.
//   MIN: zero input rows where mask==0.  MOUT: zero output rows.
//   MSK: 1 -> g_qm, 2 -> g_km (device-side selection).
//   SRC==1: A = g_QH (device ref).  DST: 0->g_QH, 1->g_KH, 2->g_VH, 3->Cext.
//   Single-buffered 128x128x16 tiling, 256 threads, 8x8 per thread.
// =====================================================================
template<bool MIN, bool MOUT, int SRC, int DST, int MSK>
__global__ __launch_bounds__(256) void sgemm_nt(
    const float* __restrict__ Aext, const float* __restrict__ W,
    const float* __restrict__ bias, float* __restrict__ Cext)
{
    const float* __restrict__ A = (SRC == 1) ? (const float*)g_QH : Aext;
    float* __restrict__ C =
        (DST == 0) ? g_QH : (DST == 1) ? g_KH : (DST == 2) ? g_VH : Cext;
    const unsigned char* __restrict__ rmask = (MSK == 1) ? g_qm : g_km;

    __shared__ float As[16][132];
    __shared__ float Bs[16][132];

    const int tid = threadIdx.x;
    const int bm = blockIdx.y * 128;
    const int bn = blockIdx.x * 128;
    const int lr = tid >> 2;          // 0..63
    const int lc = (tid & 3) << 2;    // 0,4,8,12

    float m0 = 1.f, m1 = 1.f;
    if (MIN) {
        m0 = rmask[bm + lr]      ? 1.f : 0.f;
        m1 = rmask[bm + lr + 64] ? 1.f : 0.f;
    }

    const float* A0 = A + (size_t)(bm + lr) * Ee + lc;
    const float* A1 = A0 + (size_t)64 * Ee;
    const float* W0 = W + (size_t)(bn + lr) * Ee + lc;
    const float* W1 = W0 + (size_t)64 * Ee;

    const int ty = tid >> 4, tx = tid & 15;
    float acc[8][8];
#pragma unroll
    for (int i = 0; i < 8; i++)
#pragma unroll
        for (int j = 0; j < 8; j++) acc[i][j] = 0.f;

    for (int kt = 0; kt < Ee; kt += 16) {
        float4 ra0 = *(const float4*)(A0 + kt);
        float4 ra1 = *(const float4*)(A1 + kt);
        float4 rw0 = *(const float4*)(W0 + kt);
        float4 rw1 = *(const float4*)(W1 + kt);
        __syncthreads();   // previous tile's compute done before overwrite
        As[lc + 0][lr]      = ra0.x * m0; As[lc + 1][lr]      = ra0.y * m0;
        As[lc + 2][lr]      = ra0.z * m0; As[lc + 3][lr]      = ra0.w * m0;
        As[lc + 0][lr + 64] = ra1.x * m1; As[lc + 1][lr + 64] = ra1.y * m1;
        As[lc + 2][lr + 64] = ra1.z * m1; As[lc + 3][lr + 64] = ra1.w * m1;
        Bs[lc + 0][lr]      = rw0.x;      Bs[lc + 1][lr]      = rw0.y;
        Bs[lc + 2][lr]      = rw0.z;      Bs[lc + 3][lr]      = rw0.w;
        Bs[lc + 0][lr + 64] = rw1.x;      Bs[lc + 1][lr + 64] = rw1.y;
        Bs[lc + 2][lr + 64] = rw1.z;      Bs[lc + 3][lr + 64] = rw1.w;
        __syncthreads();
#pragma unroll
        for (int kk = 0; kk < 16; kk++) {
            float a[8], w[8];
            float4 t0 = *(const float4*)&As[kk][ty * 4];
            float4 t1 = *(const float4*)&As[kk][64 + ty * 4];
            float4 u0 = *(const float4*)&Bs[kk][tx * 4];
            float4 u1 = *(const float4*)&Bs[kk][64 + tx * 4];
            a[0] = t0.x; a[1] = t0.y; a[2] = t0.z; a[3] = t0.w;
            a[4] = t1.x; a[5] = t1.y; a[6] = t1.z; a[7] = t1.w;
            w[0] = u0.x; w[1] = u0.y; w[2] = u0.z; w[3] = u0.w;
            w[4] = u1.x; w[5] = u1.y; w[6] = u1.z; w[7] = u1.w;
#pragma unroll
            for (int i = 0; i < 8; i++)
#pragma unroll
                for (int j = 0; j < 8; j++) acc[i][j] += a[i] * w[j];
        }
    }

    float4 b0 = *(const float4*)&bias[bn + tx * 4];
    float4 b1 = *(const float4*)&bias[bn + 64 + tx * 4];
#pragma unroll
    for (int i = 0; i < 8; i++) {
        const int row = bm + ((i < 4) ? (ty * 4 + i) : (64 + ty * 4 + (i - 4)));
        float rm = 1.f;
        if (MOUT) rm = rmask[row] ? 1.f : 0.f;
        float* Crow = C + (size_t)row * Ee + bn;
        float4 o0, o1;
        o0.x = (acc[i][0] + b0.x) * rm; o0.y = (acc[i][1] + b0.y) * rm;
        o0.z = (acc[i][2] + b0.z) * rm; o0.w = (acc[i][3] + b0.w) * rm;
        o1.x = (acc[i][4] + b1.x) * rm; o1.y = (acc[i][5] + b1.y) * rm;
        o1.z = (acc[i][6] + b1.z) * rm; o1.w = (acc[i][7] + b1.w) * rm;
        *(float4*)&Crow[tx * 4]      = o0;
        *(float4*)&Crow[64 + tx * 4] = o1;
    }
}

// =====================================================================
// Exact masked-k-row softmax vector: softmax_per_head(-1e9*rowsum(Wk)+bk).
// fp32 underflow makes this the exact one-hot the reference produces.
// =====================================================================
__global__ void khmask_kernel(const float* __restrict__ Wk, const float* __restrict__ bk)
{
    __shared__ float m[Ee];
    const int warp = threadIdx.x >> 5, lane = threadIdx.x & 31;
    for (int r = warp; r < Ee; r += 32) {
        float s = 0.f;
        for (int e = lane; e < Ee; e += 32) s += Wk[(size_t)r * Ee + e];
#pragma unroll
        for (int o = 16; o; o >>= 1) s += __shfl_xor_sync(0xffffffffu, s, o);
        if (lane == 0) m[r] = -1e9f * s + bk[r];
    }
    __syncthreads();
    const int t = threadIdx.x;
    if (t < Hh) {
        float mx = -3.4e38f;
        for (int d = 0; d < Dd; d++) mx = fmaxf(mx, m[t * Dd + d]);
        float sm = 0.f;
        for (int d = 0; d < Dd; d++) sm += expf(m[t * Dd + d] - mx);
        const float inv = 1.f / sm;
        for (int d = 0; d < Dd; d++) g_khm[t * Dd + d] = expf(m[t * Dd + d] - mx) * inv;
    }
}

// =====================================================================
// per-head-row softmax (64 wide), in place. ISK=false -> g_QH,
// ISK=true -> g_KH with masked rows replaced by the exact g_khm vector.
// =====================================================================
template<bool ISK>
__global__ __launch_bounds__(256) void softmax64()
{
    float* __restrict__ X = ISK ? g_KH : g_QH;
    const int warp = threadIdx.x >> 5, lane = threadIdx.x & 31;
    const size_t row = (size_t)blockIdx.x * 8 + warp;   // < 262144
    float* p = X + row * Dd;
    if (ISK) {
        if (!g_km[row >> 4]) {                          // row = (b*Ss+s)*16 + h
            const int h = (int)(row & 15);
            p[lane]      = g_khm[h * Dd + lane];
            p[lane + 32] = g_khm[h * Dd + lane + 32];
            return;
        }
    }
    float x0 = p[lane], x1 = p[lane + 32];
    float mx = fmaxf(x0, x1);
#pragma unroll
    for (int o = 16; o; o >>= 1) mx = fmaxf(mx, __shfl_xor_sync(0xffffffffu, mx, o));
    float e0 = expf(x0 - mx), e1 = expf(x1 - mx);
    float s = e0 + e1;
#pragma unroll
    for (int o = 16; o; o >>= 1) s += __shfl_xor_sync(0xffffffffu, s, o);
    const float inv = 1.f / s;
    p[lane]      = e0 * inv;
    p[lane + 32] = e1 * inv;
}

__global__ void zero_ctx_kernel()
{
    g_ctx[blockIdx.x * blockDim.x + threadIdx.x] = 0.f;
}

// k_cumsum[b,h,d] = sum_s kh[b,s,h,d]  (masked rows already hold khm)
__global__ __launch_bounds__(512) void kcum_kernel()
{
    const int bh = blockIdx.x;
    const int b = bh >> 4, h = bh & 15;
    const int d = threadIdx.x & 63;
    const int sg = threadIdx.x >> 6;   // 0..7
    float acc = 0.f;
    const float* base = g_KH + (size_t)b * Ss * Ee + h * Dd + d;
#pragma unroll 4
    for (int s = sg; s < Ss; s += 8) acc += base[(size_t)s * Ee];
    __shared__ float red[8][64];
    red[sg][d] = acc;
    __syncthreads();
    if (sg == 0) {
        float t = 0.f;
        for (int i = 0; i < 8; i++) t += red[i][d];
        g_kcum[bh * Dd + d] = t;
    }
}

// context[b,h,d,e] += sum_s kh[s,d] * vh[s,e]   (split-K over s, atomics)
__global__ __launch_bounds__(256) void context_kernel()
{
    const int bh = blockIdx.y;
    const int b = bh >> 4, h = bh & 15;
    const int s0 = blockIdx.x * 512;
    __shared__ float kh[8][64], vh[8][64];
    float acc[16];
#pragma unroll
    for (int i = 0; i < 16; i++) acc[i] = 0.f;
    const int e  = threadIdx.x & 63;
    const int dg = threadIdx.x >> 6;   // 0..3
    const int rr = threadIdx.x >> 6;
    const int cc = threadIdx.x & 63;

    for (int st = s0; st < s0 + 512; st += 8) {
        const size_t rowbase = ((size_t)b * Ss + st) * Ee + h * Dd;
        kh[rr][cc]     = g_KH[rowbase + (size_t)rr * Ee + cc];
        kh[rr + 4][cc] = g_KH[rowbase + (size_t)(rr + 4) * Ee + cc];
        vh[rr][cc]     = g_VH[rowbase + (size_t)rr * Ee + cc];
        vh[rr + 4][cc] = g_VH[rowbase + (size_t)(rr + 4) * Ee + cc];
        __syncthreads();
#pragma unroll
        for (int j = 0; j < 8; j++) {
            const float v = vh[j][e];
#pragma unroll
            for (int i = 0; i < 16; i++) acc[i] += kh[j][i * 4 + dg] * v;
        }
        __syncthreads();
    }
#pragma unroll
    for (int i = 0; i < 16; i++)
        atomicAdd(&g_ctx[((size_t)bh * Dd + (i * 4 + dg)) * Dd + e], acc[i]);
}

// out_row = (qh @ ctx) * (1 / (qh . kcum)) + qh   — in place on g_QH
__global__ __launch_bounds__(256) void combine_kernel()
{
    const int bh = blockIdx.y;
    const int b = bh >> 4, h = bh & 15;
    const int s0 = blockIdx.x * 128;
    __shared__ float ctx[64][64];
    __shared__ float kc[64];
    for (int i = threadIdx.x; i < Dd * Dd; i += 256)
        ((float*)ctx)[i] = g_ctx[(size_t)bh * Dd * Dd + i];
    if (threadIdx.x < 64) kc[threadIdx.x] = g_kcum[bh * Dd + threadIdx.x];
    __syncthreads();

    const int warp = threadIdx.x >> 5, lane = threadIdx.x & 31;
    for (int s = s0 + warp; s < s0 + 128; s += 8) {
        float* p = g_QH + ((size_t)b * Ss + s) * Ee + h * Dd;
        const float q0 = p[lane], q1 = p[lane + 32];
        float dot = q0 * kc[lane] + q1 * kc[lane + 32];
#pragma unroll
        for (int o = 16; o; o >>= 1) dot += __shfl_xor_sync(0xffffffffu, dot, o);
        const float a = 1.f / dot;
        float o0 = 0.f, o1 = 0.f;
#pragma unroll
        for (int d = 0; d < 32; d++) {
            const float qd = __shfl_sync(0xffffffffu, q0, d);
            o0 += qd * ctx[d][lane];
            o1 += qd * ctx[d][lane + 32];
        }
#pragma unroll
        for (int d = 0; d < 32; d++) {
            const float qd = __shfl_sync(0xffffffffu, q1, d);
            o0 += qd * ctx[d + 32][lane];
            o1 += qd * ctx[d + 32][lane + 32];
        }
        p[lane]      = o0 * a + q0;
        p[lane + 32] = o1 * a + q1;
    }
}

// =====================================================================
extern "C" void kernel_launch(void* const* d_in, const int* in_sizes, int n_in,
                              void* d_out, int out_size)
{
    const float* q  = (const float*)d_in[0];
    const float* k  = (const float*)d_in[1];
    const float* v  = (const float*)d_in[2];
    const unsigned char* qm_raw = (const unsigned char*)d_in[3];
    const unsigned char* km_raw = (const unsigned char*)d_in[4];
    const float* Wq = (const float*)d_in[5];
    const float* bq = (const float*)d_in[6];
    const float* Wk = (const float*)d_in[7];
    const float* bk = (const float*)d_in[8];
    const float* Wv = (const float*)d_in[9];
    const float* bv = (const float*)d_in[10];
    const float* Wp = (const float*)d_in[11];
    const float* bp = (const float*)d_in[12];
    float* out = (float*)d_out;

    // 0) normalize masks into g_qm / g_km (device-side symbols)
    norm_mask_kernel<true ><<<1, 256>>>(qm_raw, Mtot);
    norm_mask_kernel<false><<<1, 256>>>(km_raw, Mtot);

    const dim3 gg(Ee / 128, Mtot / 128);   // (8, 128)

    // 1) projections. Masked q rows -> 0 (zeroed again by output mask).
    //    Masked k/v rows -> 0 input; masked KH rows then get the exact
    //    reference one-hot; masked VH rows = bv (bias-only) as in reference.
    sgemm_nt<true,  false, 0, 0, 1><<<gg, 256>>>(q, Wq, bq, nullptr);
    sgemm_nt<true,  false, 0, 1, 2><<<gg, 256>>>(k, Wk, bk, nullptr);
    sgemm_nt<true,  false, 0, 2, 2><<<gg, 256>>>(v, Wv, bv, nullptr);

    // 2) exact masked-row kh vector, then softmaxes
    khmask_kernel<<<1, 1024>>>(Wk, bk);
    softmax64<false><<<HRows / 8, 256>>>();
    softmax64<true ><<<HRows / 8, 256>>>();

    // 3) linear-attention core
    zero_ctx_kernel<<<(Bb * Hh * Dd * Dd) / 256, 256>>>();
    kcum_kernel<<<Bb * Hh, 512>>>();
    context_kernel<<<dim3(Ss / 512, Bb * Hh), 256>>>();
    combine_kernel<<<dim3(Ss / 128, Bb * Hh), 256>>>();

    // 4) output projection + output row mask
    sgemm_nt<false, true, 1, 3, 1><<<gg, 256>>>(nullptr, Wp, bp, out);
}

// round 5
// speedup vs baseline: 1.4596x; 1.4596x over previous
#include <cuda_runtime.h>
#include <cuda_bf16.h>
#include <math.h>
#include <stdint.h>

// ---------------- problem constants ----------------
constexpr int Bb = 4;
constexpr int Ss = 4096;
constexpr int Ee = 1024;
constexpr int Hh = 16;
constexpr int Dd = 64;
constexpr int Mtot = Bb * Ss;          // 16384 projection rows
constexpr int HRows = Mtot * Hh;       // 262144 head-rows (64 wide)

// ---------------- scratch (device globals; device-code refs only) ----------------
__device__ __align__(16) float g_QH[(size_t)Mtot * Ee];
__device__ __align__(16) float g_KH[(size_t)Mtot * Ee];
__device__ __align__(16) float g_VH[(size_t)Mtot * Ee];
__device__ __align__(16) float g_ctx[Bb * Hh * Dd * Dd];
__device__ __align__(16) float g_kcum[Bb * Hh * Dd];
__device__ __align__(16) float g_khm[Ee];
__device__ unsigned char g_qm[Mtot];
__device__ unsigned char g_km[Mtot];
// split-bf16 operand buffers (A reused for q/k/v/combined; W reused per GEMM)
__device__ __align__(16) __nv_bfloat16 g_Ahi[(size_t)Mtot * Ee];
__device__ __align__(16) __nv_bfloat16 g_Alo[(size_t)Mtot * Ee];
__device__ __align__(16) __nv_bfloat16 g_Whi[(size_t)Ee * Ee];
__device__ __align__(16) __nv_bfloat16 g_Wlo[(size_t)Ee * Ee];

// =====================================================================
// helpers
// =====================================================================
__device__ __forceinline__ uint32_t smem_u32(const void* p) {
    uint32_t a;
    asm("{ .reg .u64 t; cvta.to.shared.u64 t, %1; cvt.u32.u64 %0, t; }" : "=r"(a) : "l"(p));
    return a;
}
__device__ __forceinline__ uint32_t sw64(uint32_t off) { return off ^ ((off >> 3) & 0x30); }

#define CP_ASYNC16(dst, src) \
    asm volatile("cp.async.cg.shared.global [%0], [%1], 16;" :: "r"(dst), "l"(src))
#define CP_COMMIT() asm volatile("cp.async.commit_group;" ::: "memory")
#define CP_WAIT(N)  asm volatile("cp.async.wait_group %0;" :: "n"(N) : "memory")

#define LDSM4(r, addr)                                                            \
    asm volatile("ldmatrix.sync.aligned.m8n8.x4.shared.b16 {%0,%1,%2,%3}, [%4];"  \
        : "=r"((r)[0]), "=r"((r)[1]), "=r"((r)[2]), "=r"((r)[3]) : "r"(addr))

#define MMA_BF16(d, a, b0, b1)                                                    \
    asm volatile("mma.sync.aligned.m16n8k16.row.col.f32.bf16.bf16.f32 "           \
        "{%0,%1,%2,%3}, {%4,%5,%6,%7}, {%8,%9}, {%0,%1,%2,%3};"                   \
        : "+f"((d)[0]), "+f"((d)[1]), "+f"((d)[2]), "+f"((d)[3])                  \
        : "r"((a)[0]), "r"((a)[1]), "r"((a)[2]), "r"((a)[3]), "r"(b0), "r"(b1))

__device__ __forceinline__ void split4(float4 x, uint2& hv, uint2& lv) {
    __nv_bfloat16 h0 = __float2bfloat16(x.x), h1 = __float2bfloat16(x.y);
    __nv_bfloat16 h2 = __float2bfloat16(x.z), h3 = __float2bfloat16(x.w);
    __nv_bfloat16 l0 = __float2bfloat16(x.x - __bfloat162float(h0));
    __nv_bfloat16 l1 = __float2bfloat16(x.y - __bfloat162float(h1));
    __nv_bfloat16 l2 = __float2bfloat16(x.z - __bfloat162float(h2));
    __nv_bfloat16 l3 = __float2bfloat16(x.w - __bfloat162float(h3));
    __nv_bfloat162 a{h0, h1}, b{h2, h3}, c{l0, l1}, d{l2, l3};
    hv.x = *(uint32_t*)&a; hv.y = *(uint32_t*)&b;
    lv.x = *(uint32_t*)&c; lv.y = *(uint32_t*)&d;
}

// =====================================================================
// operand pre-conversion: fp32 -> hi/lo bf16 (row mask fused for A inputs)
// MSK: 0 none, 1 g_qm, 2 g_km
// =====================================================================
template<int MSK>
__global__ __launch_bounds__(256) void conv_a(const float* __restrict__ src)
{
    const size_t i4 = (size_t)blockIdx.x * 256 + threadIdx.x;   // over Mtot*Ee/4
    float4 x = ((const float4*)src)[i4];
    const int row = (int)(i4 >> 8);                              // 256 float4 per row
    float m = 1.f;
    if (MSK == 1) m = g_qm[row] ? 1.f : 0.f;
    if (MSK == 2) m = g_km[row] ? 1.f : 0.f;
    x.x *= m; x.y *= m; x.z *= m; x.w *= m;
    uint2 hv, lv;
    split4(x, hv, lv);
    *(uint2*)&g_Ahi[i4 * 4] = hv;
    *(uint2*)&g_Alo[i4 * 4] = lv;
}

__global__ __launch_bounds__(256) void conv_w(const float* __restrict__ W)
{
    const size_t i4 = (size_t)blockIdx.x * 256 + threadIdx.x;   // over Ee*Ee/4
    float4 x = ((const float4*)W)[i4];
    uint2 hv, lv;
    split4(x, hv, lv);
    *(uint2*)&g_Whi[i4 * 4] = hv;
    *(uint2*)&g_Wlo[i4 * 4] = lv;
}

// =====================================================================
// split-bf16 tensor-core GEMM via mma.sync (HMMA):
//   C[m,n] = (sum_e A[m,e]*W[n,e] + bias[n]) * (MOUT ? qmask[m] : 1)
//   A = g_Ahi/g_Alo, B = g_Whi/g_Wlo. Virtual K = 3*1024 (hi*hi, hi*lo, lo*hi).
//   128x128 CTA tile, 8 warps (64x32 each), BK=32, 2-stage cp.async.
//   DST: 0->g_QH, 1->g_KH, 2->g_VH, 3->Cext.
// =====================================================================
template<bool MOUT, int DST>
__global__ __launch_bounds__(256, 2) void tgemm(const float* __restrict__ bias,
                                                float* __restrict__ Cext)
{
    float* __restrict__ C =
        (DST == 0) ? g_QH : (DST == 1) ? g_KH : (DST == 2) ? g_VH : Cext;

    __shared__ __align__(128) __nv_bfloat16 smA[2][4096];   // 2 x 8KB (128 rows x 64B)
    __shared__ __align__(128) __nv_bfloat16 smB[2][4096];

    const int tid  = threadIdx.x;
    const int lane = tid & 31;
    const int wid  = tid >> 5;
    const int wm   = (wid >> 2) * 64;     // warp m offset in tile
    const int wn   = (wid & 3) * 32;      // warp n offset in tile
    const int bm   = blockIdx.y * 128;
    const int bn   = blockIdx.x * 128;

    const uint32_t smA0 = smem_u32(&smA[0][0]);
    const uint32_t smB0 = smem_u32(&smB[0][0]);

    // per-thread load coords: 2 chunks of 16B for A and for B per slab
    const int ldrow = tid >> 1;           // 0..127
    const int ldseg = (tid & 1) * 2;      // 0 or 2 (two consecutive segs each)

    float acc[4][4][4];
#pragma unroll
    for (int mt = 0; mt < 4; mt++)
#pragma unroll
        for (int nt = 0; nt < 4; nt++)
#pragma unroll
            for (int i = 0; i < 4; i++) acc[mt][nt][i] = 0.f;

    auto issue = [&](int s, int st) {
        const int prod = s >> 5;
        const __nv_bfloat16* __restrict__ Ab = (prod == 2) ? g_Alo : g_Ahi;
        const __nv_bfloat16* __restrict__ Bb = (prod == 1) ? g_Wlo : g_Whi;
        const int ks = (s & 31) * 32;
#pragma unroll
        for (int i = 0; i < 2; i++) {
            const int seg = ldseg + i;
            const uint32_t so = sw64((uint32_t)(ldrow * 64 + seg * 16));
            CP_ASYNC16(smA0 + st * 8192 + so,
                       Ab + (size_t)(bm + ldrow) * Ee + ks + seg * 8);
            CP_ASYNC16(smB0 + st * 8192 + so,
                       Bb + (size_t)(bn + ldrow) * Ee + ks + seg * 8);
        }
        CP_COMMIT();
    };

    issue(0, 0);
    issue(1, 1);

    const int q = lane >> 3, r = lane & 7;

#pragma unroll 1
    for (int s = 0; s < 96; s++) {
        if (s == 95) { CP_WAIT(0); } else { CP_WAIT(1); }
        __syncthreads();
        const int st = s & 1;
        const uint32_t aB = smA0 + st * 8192;
        const uint32_t bB = smB0 + st * 8192;
#pragma unroll
        for (int kk = 0; kk < 32; kk += 16) {
            uint32_t afr[4][4], bfr[2][4];
#pragma unroll
            for (int mt = 0; mt < 4; mt++) {
                const int row = wm + mt * 16 + (q & 1) * 8 + r;
                LDSM4(afr[mt], aB + sw64((uint32_t)(row * 64 + kk * 2 + (q >> 1) * 16)));
            }
            {
                const int rowb = wn + q * 8 + r;
                LDSM4(bfr[0], bB + sw64((uint32_t)(rowb * 64 + kk * 2)));
                LDSM4(bfr[1], bB + sw64((uint32_t)(rowb * 64 + kk * 2 + 16)));
            }
#pragma unroll
            for (int mt = 0; mt < 4; mt++)
#pragma unroll
                for (int nt = 0; nt < 4; nt++)
                    MMA_BF16(acc[mt][nt], afr[mt], bfr[0][nt], bfr[1][nt]);
        }
        __syncthreads();
        if (s + 2 < 96) issue(s + 2, st);
    }

    // ---- epilogue: + bias, optional q-row mask, float2 stores ----
    const int cl = 2 * (lane & 3);
    float2 bcol[4];
#pragma unroll
    for (int nt = 0; nt < 4; nt++)
        bcol[nt] = *(const float2*)&bias[bn + wn + nt * 8 + cl];

#pragma unroll
    for (int mt = 0; mt < 4; mt++) {
        const int row0 = bm + wm + mt * 16 + (lane >> 2);
        const int row1 = row0 + 8;
        float rm0 = 1.f, rm1 = 1.f;
        if (MOUT) {
            rm0 = g_qm[row0] ? 1.f : 0.f;
            rm1 = g_qm[row1] ? 1.f : 0.f;
        }
#pragma unroll
        for (int nt = 0; nt < 4; nt++) {
            const int col = bn + wn + nt * 8 + cl;
            float2 o0, o1;
            o0.x = (acc[mt][nt][0] + bcol[nt].x) * rm0;
            o0.y = (acc[mt][nt][1] + bcol[nt].y) * rm0;
            o1.x = (acc[mt][nt][2] + bcol[nt].x) * rm1;
            o1.y = (acc[mt][nt][3] + bcol[nt].y) * rm1;
            *(float2*)&C[(size_t)row0 * Ee + col] = o0;
            *(float2*)&C[(size_t)row1 * Ee + col] = o1;
        }
    }
}

// =====================================================================
// Mask normalization (detect bool/int8 vs int32/float32 storage)
// =====================================================================
template<bool QM>
__global__ void norm_mask_kernel(const unsigned char* __restrict__ src, int n)
{
    unsigned char* dst = QM ? g_qm : g_km;
    __shared__ int vote_u8, any_nz;
    if (threadIdx.x == 0) { vote_u8 = 0; any_nz = 0; }
    __syncthreads();
    const unsigned int* w = (const unsigned int*)src;
    const int nw = n >> 2;
    int l_u8 = 0, l_nz = 0;
    for (int i = threadIdx.x; i < nw; i += blockDim.x) {
        unsigned int vv = w[i];
        if (vv != 0u) l_nz = 1;
        if (vv != 0u && vv != 1u && vv != 0x3F800000u) l_u8 = 1;
    }
    if (l_u8) vote_u8 = 1;
    if (l_nz) any_nz = 1;
    __syncthreads();
    if (!any_nz) {
        for (int i = threadIdx.x; i < n; i += blockDim.x) dst[i] = 0;
    } else if (vote_u8) {
        for (int i = threadIdx.x; i < n; i += blockDim.x) dst[i] = src[i] ? 1 : 0;
    } else {
        for (int i = threadIdx.x; i < n; i += blockDim.x) dst[i] = w[i] ? 1 : 0;
    }
}

// =====================================================================
// Exact masked-k-row softmax vector: softmax_per_head(-1e9*rowsum(Wk)+bk).
// =====================================================================
__global__ void khmask_kernel(const float* __restrict__ Wk, const float* __restrict__ bk)
{
    __shared__ float m[Ee];
    const int warp = threadIdx.x >> 5, lane = threadIdx.x & 31;
    for (int r = warp; r < Ee; r += 32) {
        float s = 0.f;
        for (int e = lane; e < Ee; e += 32) s += Wk[(size_t)r * Ee + e];
#pragma unroll
        for (int o = 16; o; o >>= 1) s += __shfl_xor_sync(0xffffffffu, s, o);
        if (lane == 0) m[r] = -1e9f * s + bk[r];
    }
    __syncthreads();
    const int t = threadIdx.x;
    if (t < Hh) {
        float mx = -3.4e38f;
        for (int d = 0; d < Dd; d++) mx = fmaxf(mx, m[t * Dd + d]);
        float sm = 0.f;
        for (int d = 0; d < Dd; d++) sm += expf(m[t * Dd + d] - mx);
        const float inv = 1.f / sm;
        for (int d = 0; d < Dd; d++) g_khm[t * Dd + d] = expf(m[t * Dd + d] - mx) * inv;
    }
}

// =====================================================================
// per-head-row softmax (64 wide), in place.
// =====================================================================
template<bool ISK>
__global__ __launch_bounds__(256) void softmax64()
{
    float* __restrict__ X = ISK ? g_KH : g_QH;
    const int warp = threadIdx.x >> 5, lane = threadIdx.x & 31;
    const size_t row = (size_t)blockIdx.x * 8 + warp;
    float* p = X + row * Dd;
    if (ISK) {
        if (!g_km[row >> 4]) {
            const int h = (int)(row & 15);
            p[lane]      = g_khm[h * Dd + lane];
            p[lane + 32] = g_khm[h * Dd + lane + 32];
            return;
        }
    }
    float x0 = p[lane], x1 = p[lane + 32];
    float mx = fmaxf(x0, x1);
#pragma unroll
    for (int o = 16; o; o >>= 1) mx = fmaxf(mx, __shfl_xor_sync(0xffffffffu, mx, o));
    float e0 = expf(x0 - mx), e1 = expf(x1 - mx);
    float s = e0 + e1;
#pragma unroll
    for (int o = 16; o; o >>= 1) s += __shfl_xor_sync(0xffffffffu, s, o);
    const float inv = 1.f / s;
    p[lane]      = e0 * inv;
    p[lane + 32] = e1 * inv;
}

__global__ void zero_ctx_kernel()
{
    g_ctx[blockIdx.x * blockDim.x + threadIdx.x] = 0.f;
}

__global__ __launch_bounds__(512) void kcum_kernel()
{
    const int bh = blockIdx.x;
    const int b = bh >> 4, h = bh & 15;
    const int d = threadIdx.x & 63;
    const int sg = threadIdx.x >> 6;
    float acc = 0.f;
    const float* base = g_KH + (size_t)b * Ss * Ee + h * Dd + d;
#pragma unroll 4
    for (int s = sg; s < Ss; s += 8) acc += base[(size_t)s * Ee];
    __shared__ float red[8][64];
    red[sg][d] = acc;
    __syncthreads();
    if (sg == 0) {
        float t = 0.f;
        for (int i = 0; i < 8; i++) t += red[i][d];
        g_kcum[bh * Dd + d] = t;
    }
}

__global__ __launch_bounds__(256) void context_kernel()
{
    const int bh = blockIdx.y;
    const int b = bh >> 4, h = bh & 15;
    const int s0 = blockIdx.x * 512;
    __shared__ float kh[8][64], vh[8][64];
    float acc[16];
#pragma unroll
    for (int i = 0; i < 16; i++) acc[i] = 0.f;
    const int e  = threadIdx.x & 63;
    const int dg = threadIdx.x >> 6;
    const int rr = threadIdx.x >> 6;
    const int cc = threadIdx.x & 63;

    for (int st = s0; st < s0 + 512; st += 8) {
        const size_t rowbase = ((size_t)b * Ss + st) * Ee + h * Dd;
        kh[rr][cc]     = g_KH[rowbase + (size_t)rr * Ee + cc];
        kh[rr + 4][cc] = g_KH[rowbase + (size_t)(rr + 4) * Ee + cc];
        vh[rr][cc]     = g_VH[rowbase + (size_t)rr * Ee + cc];
        vh[rr + 4][cc] = g_VH[rowbase + (size_t)(rr + 4) * Ee + cc];
        __syncthreads();
#pragma unroll
        for (int j = 0; j < 8; j++) {
            const float v = vh[j][e];
#pragma unroll
            for (int i = 0; i < 16; i++) acc[i] += kh[j][i * 4 + dg] * v;
        }
        __syncthreads();
    }
#pragma unroll
    for (int i = 0; i < 16; i++)
        atomicAdd(&g_ctx[((size_t)bh * Dd + (i * 4 + dg)) * Dd + e], acc[i]);
}

// out_row = (qh @ ctx) * (1/(qh.kcum)) + qh — written as hi/lo bf16 into g_Ahi/g_Alo
__global__ __launch_bounds__(256) void combine_kernel()
{
    const int bh = blockIdx.y;
    const int b = bh >> 4, h = bh & 15;
    const int s0 = blockIdx.x * 128;
    __shared__ float ctx[64][64];
    __shared__ float kc[64];
    for (int i = threadIdx.x; i < Dd * Dd; i += 256)
        ((float*)ctx)[i] = g_ctx[(size_t)bh * Dd * Dd + i];
    if (threadIdx.x < 64) kc[threadIdx.x] = g_kcum[bh * Dd + threadIdx.x];
    __syncthreads();

    const int warp = threadIdx.x >> 5, lane = threadIdx.x & 31;
    for (int s = s0 + warp; s < s0 + 128; s += 8) {
        const size_t gi = ((size_t)b * Ss + s) * Ee + h * Dd;
        const float* p = g_QH + gi;
        const float q0 = p[lane], q1 = p[lane + 32];
        float dot = q0 * kc[lane] + q1 * kc[lane + 32];
#pragma unroll
        for (int o = 16; o; o >>= 1) dot += __shfl_xor_sync(0xffffffffu, dot, o);
        const float a = 1.f / dot;
        float o0 = 0.f, o1 = 0.f;
#pragma unroll
        for (int d = 0; d < 32; d++) {
            const float qd = __shfl_sync(0xffffffffu, q0, d);
            o0 += qd * ctx[d][lane];
            o1 += qd * ctx[d][lane + 32];
        }
#pragma unroll
        for (int d = 0; d < 32; d++) {
            const float qd = __shfl_sync(0xffffffffu, q1, d);
            o0 += qd * ctx[d + 32][lane];
            o1 += qd * ctx[d + 32][lane + 32];
        }
        const float r0 = o0 * a + q0;
        const float r1 = o1 * a + q1;
        __nv_bfloat16 h0 = __float2bfloat16(r0);
        __nv_bfloat16 h1 = __float2bfloat16(r1);
        g_Ahi[gi + lane]      = h0;
        g_Ahi[gi + lane + 32] = h1;
        g_Alo[gi + lane]      = __float2bfloat16(r0 - __bfloat162float(h0));
        g_Alo[gi + lane + 32] = __float2bfloat16(r1 - __bfloat162float(h1));
    }
}

// =====================================================================
extern "C" void kernel_launch(void* const* d_in, const int* in_sizes, int n_in,
                              void* d_out, int out_size)
{
    const float* q  = (const float*)d_in[0];
    const float* k  = (const float*)d_in[1];
    const float* v  = (const float*)d_in[2];
    const unsigned char* qm_raw = (const unsigned char*)d_in[3];
    const unsigned char* km_raw = (const unsigned char*)d_in[4];
    const float* Wq = (const float*)d_in[5];
    const float* bq = (const float*)d_in[6];
    const float* Wk = (const float*)d_in[7];
    const float* bk = (const float*)d_in[8];
    const float* Wv = (const float*)d_in[9];
    const float* bv = (const float*)d_in[10];
    const float* Wp = (const float*)d_in[11];
    const float* bp = (const float*)d_in[12];
    float* out = (float*)d_out;

    // 0) normalize masks into g_qm / g_km
    norm_mask_kernel<true ><<<1, 256>>>(qm_raw, Mtot);
    norm_mask_kernel<false><<<1, 256>>>(km_raw, Mtot);

    const int gA = (Mtot * (Ee / 4)) / 256;   // conv_a grid (16384)
    const int gW = (Ee * (Ee / 4)) / 256;     // conv_w grid (1024)
    const dim3 gg(Ee / 128, Mtot / 128);      // (8, 128)

    // 1) projections on HMMA (split-bf16, fp32 accumulate)
    conv_a<1><<<gA, 256>>>(q);  conv_w<<<gW, 256>>>(Wq);
    tgemm<false, 0><<<gg, 256>>>(bq, nullptr);
    conv_a<2><<<gA, 256>>>(k);  conv_w<<<gW, 256>>>(Wk);
    tgemm<false, 1><<<gg, 256>>>(bk, nullptr);
    conv_a<2><<<gA, 256>>>(v);  conv_w<<<gW, 256>>>(Wv);
    tgemm<false, 2><<<gg, 256>>>(bv, nullptr);

    // 2) exact masked-row kh vector, then softmaxes
    khmask_kernel<<<1, 1024>>>(Wk, bk);
    softmax64<false><<<HRows / 8, 256>>>();
    softmax64<true ><<<HRows / 8, 256>>>();

    // 3) linear-attention core (combine emits hi/lo bf16 for the last GEMM)
    zero_ctx_kernel<<<(Bb * Hh * Dd * Dd) / 256, 256>>>();
    kcum_kernel<<<Bb * Hh, 512>>>();
    context_kernel<<<dim3(Ss / 512, Bb * Hh), 256>>>();
    combine_kernel<<<dim3(Ss / 128, Bb * Hh), 256>>>();

    // 4) output projection + output row mask
    conv_w<<<gW, 256>>>(Wp);
    tgemm<true, 3><<<gg, 256>>>(bp, out);
}

// round 6
// speedup vs baseline: 1.6585x; 1.1363x over previous
#include <cuda_runtime.h>
#include <cuda_bf16.h>
#include <math.h>
#include <stdint.h>

// ---------------- problem constants ----------------
constexpr int Bb = 4;
constexpr int Ss = 4096;
constexpr int Ee = 1024;
constexpr int Hh = 16;
constexpr int Dd = 64;
constexpr int Mtot = Bb * Ss;          // 16384 projection rows
constexpr int HRows = Mtot * Hh;       // 262144 head-rows (64 wide)

// ---------------- scratch (device globals; device-code refs only) ----------------
__device__ __align__(16) float g_QH[(size_t)Mtot * Ee];
__device__ __align__(16) float g_KH[(size_t)Mtot * Ee];
__device__ __align__(16) float g_VH[(size_t)Mtot * Ee];
__device__ __align__(16) float g_ctx[Bb * Hh * Dd * Dd];
__device__ __align__(16) float g_kcum[Bb * Hh * Dd];
__device__ __align__(16) float g_khm[Ee];
__device__ unsigned char g_qm[Mtot];
__device__ unsigned char g_km[Mtot];
__device__ __align__(16) __nv_bfloat16 g_Ahi[(size_t)Mtot * Ee];
__device__ __align__(16) __nv_bfloat16 g_Alo[(size_t)Mtot * Ee];
__device__ __align__(16) __nv_bfloat16 g_Whi[(size_t)Ee * Ee];
__device__ __align__(16) __nv_bfloat16 g_Wlo[(size_t)Ee * Ee];

// =====================================================================
// helpers
// =====================================================================
__device__ __forceinline__ uint32_t smem_u32(const void* p) {
    uint32_t a;
    asm("{ .reg .u64 t; cvta.to.shared.u64 t, %1; cvt.u32.u64 %0, t; }" : "=r"(a) : "l"(p));
    return a;
}
__device__ __forceinline__ uint32_t sw64(uint32_t off) { return off ^ ((off >> 3) & 0x30); }

#define CP_ASYNC16(dst, src) \
    asm volatile("cp.async.cg.shared.global [%0], [%1], 16;" :: "r"(dst), "l"(src))
#define CP_COMMIT() asm volatile("cp.async.commit_group;" ::: "memory")
#define CP_WAIT(N)  asm volatile("cp.async.wait_group %0;" :: "n"(N) : "memory")

#define LDSM4(r, addr)                                                            \
    asm volatile("ldmatrix.sync.aligned.m8n8.x4.shared.b16 {%0,%1,%2,%3}, [%4];"  \
        : "=r"((r)[0]), "=r"((r)[1]), "=r"((r)[2]), "=r"((r)[3]) : "r"(addr))

#define MMA_BF16(d, a, b0, b1)                                                    \
    asm volatile("mma.sync.aligned.m16n8k16.row.col.f32.bf16.bf16.f32 "           \
        "{%0,%1,%2,%3}, {%4,%5,%6,%7}, {%8,%9}, {%0,%1,%2,%3};"                   \
        : "+f"((d)[0]), "+f"((d)[1]), "+f"((d)[2]), "+f"((d)[3])                  \
        : "r"((a)[0]), "r"((a)[1]), "r"((a)[2]), "r"((a)[3]), "r"(b0), "r"(b1))

__device__ __forceinline__ void split4(float4 x, uint2& hv, uint2& lv) {
    __nv_bfloat16 h0 = __float2bfloat16(x.x), h1 = __float2bfloat16(x.y);
    __nv_bfloat16 h2 = __float2bfloat16(x.z), h3 = __float2bfloat16(x.w);
    __nv_bfloat16 l0 = __float2bfloat16(x.x - __bfloat162float(h0));
    __nv_bfloat16 l1 = __float2bfloat16(x.y - __bfloat162float(h1));
    __nv_bfloat16 l2 = __float2bfloat16(x.z - __bfloat162float(h2));
    __nv_bfloat16 l3 = __float2bfloat16(x.w - __bfloat162float(h3));
    __nv_bfloat162 a{h0, h1}, b{h2, h3}, c{l0, l1}, d{l2, l3};
    hv.x = *(uint32_t*)&a; hv.y = *(uint32_t*)&b;
    lv.x = *(uint32_t*)&c; lv.y = *(uint32_t*)&d;
}

// =====================================================================
// operand pre-conversion: fp32 -> hi/lo bf16 (row mask fused for A inputs)
// =====================================================================
template<int MSK>
__global__ __launch_bounds__(256) void conv_a(const float* __restrict__ src)
{
    const size_t i4 = (size_t)blockIdx.x * 256 + threadIdx.x;
    float4 x = ((const float4*)src)[i4];
    const int row = (int)(i4 >> 8);
    float m = 1.f;
    if (MSK == 1) m = g_qm[row] ? 1.f : 0.f;
    if (MSK == 2) m = g_km[row] ? 1.f : 0.f;
    x.x *= m; x.y *= m; x.z *= m; x.w *= m;
    uint2 hv, lv;
    split4(x, hv, lv);
    *(uint2*)&g_Ahi[i4 * 4] = hv;
    *(uint2*)&g_Alo[i4 * 4] = lv;
}

__global__ __launch_bounds__(256) void conv_w(const float* __restrict__ W)
{
    const size_t i4 = (size_t)blockIdx.x * 256 + threadIdx.x;
    float4 x = ((const float4*)W)[i4];
    uint2 hv, lv;
    split4(x, hv, lv);
    *(uint2*)&g_Whi[i4 * 4] = hv;
    *(uint2*)&g_Wlo[i4 * 4] = lv;
}

// =====================================================================
// split-bf16 tensor-core GEMM via mma.sync (HMMA), 3-stage cp.async pipe.
//   Virtual K = 3*1024: slabs 0..31 hi*hi, 32..63 hi*lo, 64..95 lo*hi.
//   128x128 CTA tile, 8 warps (64x32), BK=32, ONE syncthreads per slab.
// =====================================================================
template<bool MOUT, int DST>
__global__ __launch_bounds__(256, 2) void tgemm(const float* __restrict__ bias,
                                                float* __restrict__ Cext)
{
    float* __restrict__ C =
        (DST == 0) ? g_QH : (DST == 1) ? g_KH : (DST == 2) ? g_VH : Cext;

    __shared__ __align__(128) __nv_bfloat16 smA[3][4096];   // 3 x 8KB
    __shared__ __align__(128) __nv_bfloat16 smB[3][4096];

    const int tid  = threadIdx.x;
    const int lane = tid & 31;
    const int wid  = tid >> 5;
    const int wm   = (wid >> 2) * 64;
    const int wn   = (wid & 3) * 32;
    const int bm   = blockIdx.y * 128;
    const int bn   = blockIdx.x * 128;

    const uint32_t smA0 = smem_u32(&smA[0][0]);
    const uint32_t smB0 = smem_u32(&smB[0][0]);

    const int ldrow = tid >> 1;
    const int ldseg = (tid & 1) * 2;

    float acc[4][4][4];
#pragma unroll
    for (int mt = 0; mt < 4; mt++)
#pragma unroll
        for (int nt = 0; nt < 4; nt++)
#pragma unroll
            for (int i = 0; i < 4; i++) acc[mt][nt][i] = 0.f;

    auto issue = [&](int s, int st) {
        const int prod = s >> 5;
        const __nv_bfloat16* __restrict__ Ab = (prod == 2) ? g_Alo : g_Ahi;
        const __nv_bfloat16* __restrict__ Bb = (prod == 1) ? g_Wlo : g_Whi;
        const int ks = (s & 31) * 32;
#pragma unroll
        for (int i = 0; i < 2; i++) {
            const int seg = ldseg + i;
            const uint32_t so = sw64((uint32_t)(ldrow * 64 + seg * 16));
            CP_ASYNC16(smA0 + st * 8192 + so,
                       Ab + (size_t)(bm + ldrow) * Ee + ks + seg * 8);
            CP_ASYNC16(smB0 + st * 8192 + so,
                       Bb + (size_t)(bn + ldrow) * Ee + ks + seg * 8);
        }
        CP_COMMIT();
    };

    issue(0, 0);
    issue(1, 1);

    const int q = lane >> 3, r = lane & 7;

#pragma unroll 1
    for (int s = 0; s < 96; s++) {
        if (s < 95) { CP_WAIT(1); } else { CP_WAIT(0); }
        __syncthreads();
        const int st = s % 3;
        const uint32_t aB = smA0 + st * 8192;
        const uint32_t bB = smB0 + st * 8192;
#pragma unroll
        for (int kk = 0; kk < 32; kk += 16) {
            uint32_t afr[4][4], bfr[2][4];
#pragma unroll
            for (int mt = 0; mt < 4; mt++) {
                const int row = wm + mt * 16 + (q & 1) * 8 + r;
                LDSM4(afr[mt], aB + sw64((uint32_t)(row * 64 + kk * 2 + (q >> 1) * 16)));
            }
            {
                const int rowb = wn + q * 8 + r;
                LDSM4(bfr[0], bB + sw64((uint32_t)(rowb * 64 + kk * 2)));
                LDSM4(bfr[1], bB + sw64((uint32_t)(rowb * 64 + kk * 2 + 16)));
            }
#pragma unroll
            for (int mt = 0; mt < 4; mt++)
#pragma unroll
                for (int nt = 0; nt < 4; nt++)
                    MMA_BF16(acc[mt][nt], afr[mt], bfr[0][nt], bfr[1][nt]);
        }
        if (s + 2 < 96) issue(s + 2, (s + 2) % 3);
    }

    // ---- epilogue: + bias, optional q-row mask ----
    const int cl = 2 * (lane & 3);
    float2 bcol[4];
#pragma unroll
    for (int nt = 0; nt < 4; nt++)
        bcol[nt] = *(const float2*)&bias[bn + wn + nt * 8 + cl];

#pragma unroll
    for (int mt = 0; mt < 4; mt++) {
        const int row0 = bm + wm + mt * 16 + (lane >> 2);
        const int row1 = row0 + 8;
        float rm0 = 1.f, rm1 = 1.f;
        if (MOUT) {
            rm0 = g_qm[row0] ? 1.f : 0.f;
            rm1 = g_qm[row1] ? 1.f : 0.f;
        }
#pragma unroll
        for (int nt = 0; nt < 4; nt++) {
            const int col = bn + wn + nt * 8 + cl;
            float2 o0, o1;
            o0.x = (acc[mt][nt][0] + bcol[nt].x) * rm0;
            o0.y = (acc[mt][nt][1] + bcol[nt].y) * rm0;
            o1.x = (acc[mt][nt][2] + bcol[nt].x) * rm1;
            o1.y = (acc[mt][nt][3] + bcol[nt].y) * rm1;
            *(float2*)&C[(size_t)row0 * Ee + col] = o0;
            *(float2*)&C[(size_t)row1 * Ee + col] = o1;
        }
    }
}

// =====================================================================
// Mask normalization
// =====================================================================
template<bool QM>
__global__ void norm_mask_kernel(const unsigned char* __restrict__ src, int n)
{
    unsigned char* dst = QM ? g_qm : g_km;
    __shared__ int vote_u8, any_nz;
    if (threadIdx.x == 0) { vote_u8 = 0; any_nz = 0; }
    __syncthreads();
    const unsigned int* w = (const unsigned int*)src;
    const int nw = n >> 2;
    int l_u8 = 0, l_nz = 0;
    for (int i = threadIdx.x; i < nw; i += blockDim.x) {
        unsigned int vv = w[i];
        if (vv != 0u) l_nz = 1;
        if (vv != 0u && vv != 1u && vv != 0x3F800000u) l_u8 = 1;
    }
    if (l_u8) vote_u8 = 1;
    if (l_nz) any_nz = 1;
    __syncthreads();
    if (!any_nz) {
        for (int i = threadIdx.x; i < n; i += blockDim.x) dst[i] = 0;
    } else if (vote_u8) {
        for (int i = threadIdx.x; i < n; i += blockDim.x) dst[i] = src[i] ? 1 : 0;
    } else {
        for (int i = threadIdx.x; i < n; i += blockDim.x) dst[i] = w[i] ? 1 : 0;
    }
}

// =====================================================================
// Exact masked-k-row softmax vector
// =====================================================================
__global__ void khmask_kernel(const float* __restrict__ Wk, const float* __restrict__ bk)
{
    __shared__ float m[Ee];
    const int warp = threadIdx.x >> 5, lane = threadIdx.x & 31;
    for (int r = warp; r < Ee; r += 32) {
        float s = 0.f;
        for (int e = lane; e < Ee; e += 32) s += Wk[(size_t)r * Ee + e];
#pragma unroll
        for (int o = 16; o; o >>= 1) s += __shfl_xor_sync(0xffffffffu, s, o);
        if (lane == 0) m[r] = -1e9f * s + bk[r];
    }
    __syncthreads();
    const int t = threadIdx.x;
    if (t < Hh) {
        float mx = -3.4e38f;
        for (int d = 0; d < Dd; d++) mx = fmaxf(mx, m[t * Dd + d]);
        float sm = 0.f;
        for (int d = 0; d < Dd; d++) sm += expf(m[t * Dd + d] - mx);
        const float inv = 1.f / sm;
        for (int d = 0; d < Dd; d++) g_khm[t * Dd + d] = expf(m[t * Dd + d] - mx) * inv;
    }
}

// =====================================================================
// per-head-row softmax (64 wide), in place.
// =====================================================================
template<bool ISK>
__global__ __launch_bounds__(256) void softmax64()
{
    float* __restrict__ X = ISK ? g_KH : g_QH;
    const int warp = threadIdx.x >> 5, lane = threadIdx.x & 31;
    const size_t row = (size_t)blockIdx.x * 8 + warp;
    float* p = X + row * Dd;
    if (ISK) {
        if (!g_km[row >> 4]) {
            const int h = (int)(row & 15);
            p[lane]      = g_khm[h * Dd + lane];
            p[lane + 32] = g_khm[h * Dd + lane + 32];
            return;
        }
    }
    float x0 = p[lane], x1 = p[lane + 32];
    float mx = fmaxf(x0, x1);
#pragma unroll
    for (int o = 16; o; o >>= 1) mx = fmaxf(mx, __shfl_xor_sync(0xffffffffu, mx, o));
    float e0 = expf(x0 - mx), e1 = expf(x1 - mx);
    float s = e0 + e1;
#pragma unroll
    for (int o = 16; o; o >>= 1) s += __shfl_xor_sync(0xffffffffu, s, o);
    const float inv = 1.f / s;
    p[lane]      = e0 * inv;
    p[lane + 32] = e1 * inv;
}

// zero g_ctx (262144) and g_kcum (4096)
constexpr int ZTOT = Bb * Hh * Dd * Dd + Bb * Hh * Dd;
__global__ void zero_kernel()
{
    const int i = blockIdx.x * 256 + threadIdx.x;
    if (i < Bb * Hh * Dd * Dd) g_ctx[i] = 0.f;
    else if (i < ZTOT) g_kcum[i - Bb * Hh * Dd * Dd] = 0.f;
}

// =====================================================================
// context[b,h,d,e] += sum_s kh[s,d]*vh[s,e]; also folds kcum[d] += kh[s,d].
// 4x4 register blocking, cp.async 3-stage tiles of 16 s-rows, grid (16, 64).
// =====================================================================
__global__ __launch_bounds__(256) void context_kernel()
{
    const int bh = blockIdx.y;
    const int b = bh >> 4, h = bh & 15;
    const int s0 = blockIdx.x * 256;
    __shared__ __align__(16) float kh[3][16][64];
    __shared__ __align__(16) float vh[3][16][64];

    const int tid  = threadIdx.x;
    const int dB   = (tid >> 4) * 4;
    const int eB   = (tid & 15) * 4;
    const int lrow = tid >> 4;        // 0..15
    const int lseg = tid & 15;        // 16B segment
    const uint32_t kB = smem_u32(&kh[0][0][0]);
    const uint32_t vB = smem_u32(&vh[0][0][0]);

    auto issue = [&](int t, int st) {
        const size_t g = ((size_t)(b * Ss + s0 + t * 16 + lrow)) * Ee + h * Dd + lseg * 4;
        CP_ASYNC16(kB + st * 4096 + lrow * 256 + lseg * 16, g_KH + g);
        CP_ASYNC16(vB + st * 4096 + lrow * 256 + lseg * 16, g_VH + g);
        CP_COMMIT();
    };

    float acc[4][4];
#pragma unroll
    for (int i = 0; i < 4; i++)
#pragma unroll
        for (int l = 0; l < 4; l++) acc[i][l] = 0.f;
    float kcp[4] = {0.f, 0.f, 0.f, 0.f};

    issue(0, 0);
    issue(1, 1);
#pragma unroll 1
    for (int t = 0; t < 16; t++) {
        if (t < 15) { CP_WAIT(1); } else { CP_WAIT(0); }
        __syncthreads();
        const int st = t % 3;
#pragma unroll
        for (int j = 0; j < 16; j++) {
            const float4 kv = *(const float4*)&kh[st][j][dB];
            const float4 vv = *(const float4*)&vh[st][j][eB];
            kcp[0] += kv.x; kcp[1] += kv.y; kcp[2] += kv.z; kcp[3] += kv.w;
            acc[0][0] += kv.x * vv.x; acc[0][1] += kv.x * vv.y;
            acc[0][2] += kv.x * vv.z; acc[0][3] += kv.x * vv.w;
            acc[1][0] += kv.y * vv.x; acc[1][1] += kv.y * vv.y;
            acc[1][2] += kv.y * vv.z; acc[1][3] += kv.y * vv.w;
            acc[2][0] += kv.z * vv.x; acc[2][1] += kv.z * vv.y;
            acc[2][2] += kv.z * vv.z; acc[2][3] += kv.z * vv.w;
            acc[3][0] += kv.w * vv.x; acc[3][1] += kv.w * vv.y;
            acc[3][2] += kv.w * vv.z; acc[3][3] += kv.w * vv.w;
        }
        if (t + 2 < 16) issue(t + 2, (t + 2) % 3);
    }

    float* ctx = g_ctx + (size_t)bh * Dd * Dd;
#pragma unroll
    for (int i = 0; i < 4; i++)
#pragma unroll
        for (int l = 0; l < 4; l++)
            atomicAdd(&ctx[(dB + i) * Dd + eB + l], acc[i][l]);
    if ((tid & 15) == 0) {
#pragma unroll
        for (int i = 0; i < 4; i++)
            atomicAdd(&g_kcum[bh * Dd + dB + i], kcp[i]);
    }
}

// out_row = (qh @ ctx) * (1/(qh.kcum)) + qh — emits hi/lo bf16 into g_Ahi/g_Alo
__global__ __launch_bounds__(256) void combine_kernel()
{
    const int bh = blockIdx.y;
    const int b = bh >> 4, h = bh & 15;
    const int s0 = blockIdx.x * 128;
    __shared__ float ctx[64][64];
    __shared__ float kc[64];
    for (int i = threadIdx.x; i < Dd * Dd; i += 256)
        ((float*)ctx)[i] = g_ctx[(size_t)bh * Dd * Dd + i];
    if (threadIdx.x < 64) kc[threadIdx.x] = g_kcum[bh * Dd + threadIdx.x];
    __syncthreads();

    const int warp = threadIdx.x >> 5, lane = threadIdx.x & 31;
    for (int s = s0 + warp; s < s0 + 128; s += 8) {
        const size_t gi = ((size_t)b * Ss + s) * Ee + h * Dd;
        const float* p = g_QH + gi;
        const float q0 = p[lane], q1 = p[lane + 32];
        float dot = q0 * kc[lane] + q1 * kc[lane + 32];
#pragma unroll
        for (int o = 16; o; o >>= 1) dot += __shfl_xor_sync(0xffffffffu, dot, o);
        const float a = 1.f / dot;
        float o0 = 0.f, o1 = 0.f;
#pragma unroll
        for (int d = 0; d < 32; d++) {
            const float qd = __shfl_sync(0xffffffffu, q0, d);
            o0 += qd * ctx[d][lane];
            o1 += qd * ctx[d][lane + 32];
        }
#pragma unroll
        for (int d = 0; d < 32; d++) {
            const float qd = __shfl_sync(0xffffffffu, q1, d);
            o0 += qd * ctx[d + 32][lane];
            o1 += qd * ctx[d + 32][lane + 32];
        }
        const float r0 = o0 * a + q0;
        const float r1 = o1 * a + q1;
        __nv_bfloat16 h0 = __float2bfloat16(r0);
        __nv_bfloat16 h1 = __float2bfloat16(r1);
        g_Ahi[gi + lane]      = h0;
        g_Ahi[gi + lane + 32] = h1;
        g_Alo[gi + lane]      = __float2bfloat16(r0 - __bfloat162float(h0));
        g_Alo[gi + lane + 32] = __float2bfloat16(r1 - __bfloat162float(h1));
    }
}

// =====================================================================
extern "C" void kernel_launch(void* const* d_in, const int* in_sizes, int n_in,
                              void* d_out, int out_size)
{
    const float* q  = (const float*)d_in[0];
    const float* k  = (const float*)d_in[1];
    const float* v  = (const float*)d_in[2];
    const unsigned char* qm_raw = (const unsigned char*)d_in[3];
    const unsigned char* km_raw = (const unsigned char*)d_in[4];
    const float* Wq = (const float*)d_in[5];
    const float* bq = (const float*)d_in[6];
    const float* Wk = (const float*)d_in[7];
    const float* bk = (const float*)d_in[8];
    const float* Wv = (const float*)d_in[9];
    const float* bv = (const float*)d_in[10];
    const float* Wp = (const float*)d_in[11];
    const float* bp = (const float*)d_in[12];
    float* out = (float*)d_out;

    // 0) normalize masks
    norm_mask_kernel<true ><<<1, 256>>>(qm_raw, Mtot);
    norm_mask_kernel<false><<<1, 256>>>(km_raw, Mtot);

    const int gA = (Mtot * (Ee / 4)) / 256;   // 16384
    const int gW = (Ee * (Ee / 4)) / 256;     // 1024
    const dim3 gg(Ee / 128, Mtot / 128);      // (8, 128)

    // 1) projections on HMMA (split-bf16, fp32 accumulate)
    conv_a<1><<<gA, 256>>>(q);  conv_w<<<gW, 256>>>(Wq);
    tgemm<false, 0><<<gg, 256>>>(bq, nullptr);
    conv_a<2><<<gA, 256>>>(k);  conv_w<<<gW, 256>>>(Wk);
    tgemm<false, 1><<<gg, 256>>>(bk, nullptr);
    conv_a<2><<<gA, 256>>>(v);  conv_w<<<gW, 256>>>(Wv);
    tgemm<false, 2><<<gg, 256>>>(bv, nullptr);

    // 2) exact masked-row kh vector, then softmaxes
    khmask_kernel<<<1, 1024>>>(Wk, bk);
    softmax64<false><<<HRows / 8, 256>>>();
    softmax64<true ><<<HRows / 8, 256>>>();

    // 3) linear-attention core (context folds kcum; combine emits hi/lo bf16)
    zero_kernel<<<(ZTOT + 255) / 256, 256>>>();
    context_kernel<<<dim3(16, Bb * Hh), 256>>>();
    combine_kernel<<<dim3(Ss / 128, Bb * Hh), 256>>>();

    // 4) output projection + output row mask
    conv_w<<<gW, 256>>>(Wp);
    tgemm<true, 3><<<gg, 256>>>(bp, out);
}

// round 7
// speedup vs baseline: 1.7140x; 1.0334x over previous
#include <cuda_runtime.h>
#include <cuda_bf16.h>
#include <math.h>
#include <stdint.h>

// ---------------- problem constants ----------------
constexpr int Bb = 4;
constexpr int Ss = 4096;
constexpr int Ee = 1024;
constexpr int Hh = 16;
constexpr int Dd = 64;
constexpr int Mtot = Bb * Ss;          // 16384 projection rows
constexpr int HRows = Mtot * Hh;

// ---------------- scratch (device globals; device-code refs only) ----------------
__device__ __align__(16) float g_QH[(size_t)Mtot * Ee];
__device__ __align__(16) float g_KH[(size_t)Mtot * Ee];
__device__ __align__(16) float g_VH[(size_t)Mtot * Ee];
__device__ __align__(16) float g_ctx[Bb * Hh * Dd * Dd];
__device__ __align__(16) float g_kcum[Bb * Hh * Dd];
__device__ __align__(16) float g_khm[Ee];
__device__ unsigned char g_qm[Mtot];
__device__ unsigned char g_km[Mtot];
__device__ __align__(16) __nv_bfloat16 g_Ahi[(size_t)Mtot * Ee];
__device__ __align__(16) __nv_bfloat16 g_Alo[(size_t)Mtot * Ee];
__device__ __align__(16) __nv_bfloat16 g_Whi[(size_t)Ee * Ee];
__device__ __align__(16) __nv_bfloat16 g_Wlo[(size_t)Ee * Ee];

// =====================================================================
// helpers
// =====================================================================
__device__ __forceinline__ uint32_t smem_u32(const void* p) {
    uint32_t a;
    asm("{ .reg .u64 t; cvta.to.shared.u64 t, %1; cvt.u32.u64 %0, t; }" : "=r"(a) : "l"(p));
    return a;
}
__device__ __forceinline__ uint32_t sw64(uint32_t off) { return off ^ ((off >> 3) & 0x30); }

#define CP_ASYNC16(dst, src) \
    asm volatile("cp.async.cg.shared.global [%0], [%1], 16;" :: "r"(dst), "l"(src))
#define CP_COMMIT() asm volatile("cp.async.commit_group;" ::: "memory")
#define CP_WAIT(N)  asm volatile("cp.async.wait_group %0;" :: "n"(N) : "memory")

#define LDSM4(r, addr)                                                            \
    asm volatile("ldmatrix.sync.aligned.m8n8.x4.shared.b16 {%0,%1,%2,%3}, [%4];"  \
        : "=r"((r)[0]), "=r"((r)[1]), "=r"((r)[2]), "=r"((r)[3]) : "r"(addr))

#define MMA_BF16(d, a, b0, b1)                                                    \
    asm volatile("mma.sync.aligned.m16n8k16.row.col.f32.bf16.bf16.f32 "           \
        "{%0,%1,%2,%3}, {%4,%5,%6,%7}, {%8,%9}, {%0,%1,%2,%3};"                   \
        : "+f"((d)[0]), "+f"((d)[1]), "+f"((d)[2]), "+f"((d)[3])                  \
        : "r"((a)[0]), "r"((a)[1]), "r"((a)[2]), "r"((a)[3]), "r"(b0), "r"(b1))

__device__ __forceinline__ void split4(float4 x, uint2& hv, uint2& lv) {
    __nv_bfloat16 h0 = __float2bfloat16(x.x), h1 = __float2bfloat16(x.y);
    __nv_bfloat16 h2 = __float2bfloat16(x.z), h3 = __float2bfloat16(x.w);
    __nv_bfloat16 l0 = __float2bfloat16(x.x - __bfloat162float(h0));
    __nv_bfloat16 l1 = __float2bfloat16(x.y - __bfloat162float(h1));
    __nv_bfloat16 l2 = __float2bfloat16(x.z - __bfloat162float(h2));
    __nv_bfloat16 l3 = __float2bfloat16(x.w - __bfloat162float(h3));
    __nv_bfloat162 a{h0, h1}, b{h2, h3}, c{l0, l1}, d{l2, l3};
    hv.x = *(uint32_t*)&a; hv.y = *(uint32_t*)&b;
    lv.x = *(uint32_t*)&c; lv.y = *(uint32_t*)&d;
}

// =====================================================================
// operand pre-conversion: fp32 -> hi/lo bf16 (row mask fused), 8 float4/thread
// =====================================================================
template<int MSK>
__global__ __launch_bounds__(256) void conv_a(const float* __restrict__ src)
{
    const size_t base = (size_t)blockIdx.x * 256 + threadIdx.x;
    constexpr size_t stride = 2048u * 256u;
    float4 xs[8];
#pragma unroll
    for (int it = 0; it < 8; it++)
        xs[it] = ((const float4*)src)[base + (size_t)it * stride];
#pragma unroll
    for (int it = 0; it < 8; it++) {
        const size_t i4 = base + (size_t)it * stride;
        const int row = (int)(i4 >> 8);
        float m = 1.f;
        if (MSK == 1) m = g_qm[row] ? 1.f : 0.f;
        if (MSK == 2) m = g_km[row] ? 1.f : 0.f;
        float4 x = xs[it];
        x.x *= m; x.y *= m; x.z *= m; x.w *= m;
        uint2 hv, lv;
        split4(x, hv, lv);
        *(uint2*)&g_Ahi[i4 * 4] = hv;
        *(uint2*)&g_Alo[i4 * 4] = lv;
    }
}

__global__ __launch_bounds__(256) void conv_w(const float* __restrict__ W)
{
    const size_t base = (size_t)blockIdx.x * 256 + threadIdx.x;
    constexpr size_t stride = 128u * 256u;
    float4 xs[8];
#pragma unroll
    for (int it = 0; it < 8; it++)
        xs[it] = ((const float4*)W)[base + (size_t)it * stride];
#pragma unroll
    for (int it = 0; it < 8; it++) {
        const size_t i4 = base + (size_t)it * stride;
        uint2 hv, lv;
        split4(xs[it], hv, lv);
        *(uint2*)&g_Whi[i4 * 4] = hv;
        *(uint2*)&g_Wlo[i4 * 4] = lv;
    }
}

// =====================================================================
// split-bf16 HMMA GEMM with fused epilogue.
//   EPI: 0 plain (+bias), 1 softmax64 (+bias), 2 softmax64 + masked-row khm
//        substitution (K path), 3 +bias then q-row output mask (final).
//   Virtual K = 3*1024 (hi*hi, hi*lo, lo*hi). 128x128 tile, 8 warps, BK=32,
//   3-stage cp.async, one syncthreads per slab.
// =====================================================================
template<int EPI, int DST>
__global__ __launch_bounds__(256, 2) void tgemm(const float* __restrict__ bias,
                                                float* __restrict__ Cext)
{
    float* __restrict__ C =
        (DST == 0) ? g_QH : (DST == 1) ? g_KH : (DST == 2) ? g_VH : Cext;

    __shared__ __align__(128) __nv_bfloat16 smA[3][4096];   // 3 x 8KB
    __shared__ __align__(128) __nv_bfloat16 smB[3][4096];

    const int tid  = threadIdx.x;
    const int lane = tid & 31;
    const int wid  = tid >> 5;
    const int wm   = (wid >> 2) * 64;
    const int wn   = (wid & 3) * 32;
    const int bm   = blockIdx.y * 128;
    const int bn   = blockIdx.x * 128;

    const uint32_t smA0 = smem_u32(&smA[0][0]);
    const uint32_t smB0 = smem_u32(&smB[0][0]);

    const int ldrow = tid >> 1;
    const int ldseg = (tid & 1) * 2;

    float acc[4][4][4];
#pragma unroll
    for (int mt = 0; mt < 4; mt++)
#pragma unroll
        for (int nt = 0; nt < 4; nt++)
#pragma unroll
            for (int i = 0; i < 4; i++) acc[mt][nt][i] = 0.f;

    auto issue = [&](int s, int st) {
        const int prod = s >> 5;
        const __nv_bfloat16* __restrict__ Ab = (prod == 2) ? g_Alo : g_Ahi;
        const __nv_bfloat16* __restrict__ Bb = (prod == 1) ? g_Wlo : g_Whi;
        const int ks = (s & 31) * 32;
#pragma unroll
        for (int i = 0; i < 2; i++) {
            const int seg = ldseg + i;
            const uint32_t so = sw64((uint32_t)(ldrow * 64 + seg * 16));
            CP_ASYNC16(smA0 + st * 8192 + so,
                       Ab + (size_t)(bm + ldrow) * Ee + ks + seg * 8);
            CP_ASYNC16(smB0 + st * 8192 + so,
                       Bb + (size_t)(bn + ldrow) * Ee + ks + seg * 8);
        }
        CP_COMMIT();
    };

    issue(0, 0);
    issue(1, 1);

    const int q = lane >> 3, r = lane & 7;

#pragma unroll 1
    for (int s = 0; s < 96; s++) {
        if (s < 95) { CP_WAIT(1); } else { CP_WAIT(0); }
        __syncthreads();
        const int st = s % 3;
        const uint32_t aB = smA0 + st * 8192;
        const uint32_t bB = smB0 + st * 8192;
#pragma unroll
        for (int kk = 0; kk < 32; kk += 16) {
            uint32_t afr[4][4], bfr[2][4];
#pragma unroll
            for (int mt = 0; mt < 4; mt++) {
                const int row = wm + mt * 16 + (q & 1) * 8 + r;
                LDSM4(afr[mt], aB + sw64((uint32_t)(row * 64 + kk * 2 + (q >> 1) * 16)));
            }
            {
                const int rowb = wn + q * 8 + r;
                LDSM4(bfr[0], bB + sw64((uint32_t)(rowb * 64 + kk * 2)));
                LDSM4(bfr[1], bB + sw64((uint32_t)(rowb * 64 + kk * 2 + 16)));
            }
#pragma unroll
            for (int mt = 0; mt < 4; mt++)
#pragma unroll
                for (int nt = 0; nt < 4; nt++)
                    MMA_BF16(acc[mt][nt], afr[mt], bfr[0][nt], bfr[1][nt]);
        }
        if (s + 2 < 96) issue(s + 2, (s + 2) % 3);
    }

    // ================= epilogue =================
    __syncthreads();   // operand smem dead; safe to reuse for reductions

    const int cl = 2 * (lane & 3);
    // bias add (all modes)
#pragma unroll
    for (int nt = 0; nt < 4; nt++) {
        const float2 bb = *(const float2*)&bias[bn + wn + nt * 8 + cl];
#pragma unroll
        for (int mt = 0; mt < 4; mt++) {
            acc[mt][nt][0] += bb.x; acc[mt][nt][1] += bb.y;
            acc[mt][nt][2] += bb.x; acc[mt][nt][3] += bb.y;
        }
    }

    if (EPI == 1 || EPI == 2) {
        float* redmax = (float*)&smA[0][0];        // [8 warps][64 rows-in-band]
        float* redsum = redmax + 512;
        const int rbase = (lane >> 2);
        float inv[4][2];

        // ---- row max (32 cols per warp, then cross-warp pair) ----
#pragma unroll
        for (int mt = 0; mt < 4; mt++)
#pragma unroll
            for (int hf = 0; hf < 2; hf++) {
                float m = -3.4e38f;
#pragma unroll
                for (int nt = 0; nt < 4; nt++)
                    m = fmaxf(m, fmaxf(acc[mt][nt][2 * hf], acc[mt][nt][2 * hf + 1]));
                m = fmaxf(m, __shfl_xor_sync(0xffffffffu, m, 1));
                m = fmaxf(m, __shfl_xor_sync(0xffffffffu, m, 2));
                if ((lane & 3) == 0)
                    redmax[wid * 64 + mt * 16 + hf * 8 + rbase] = m;
            }
        __syncthreads();
        // ---- exp + row sum ----
#pragma unroll
        for (int mt = 0; mt < 4; mt++)
#pragma unroll
            for (int hf = 0; hf < 2; hf++) {
                const int idx = mt * 16 + hf * 8 + rbase;
                const float rm = fmaxf(redmax[wid * 64 + idx],
                                       redmax[(wid ^ 1) * 64 + idx]);
                float s = 0.f;
#pragma unroll
                for (int nt = 0; nt < 4; nt++) {
                    float a0 = __expf(acc[mt][nt][2 * hf]     - rm);
                    float a1 = __expf(acc[mt][nt][2 * hf + 1] - rm);
                    acc[mt][nt][2 * hf] = a0; acc[mt][nt][2 * hf + 1] = a1;
                    s += a0 + a1;
                }
                s += __shfl_xor_sync(0xffffffffu, s, 1);
                s += __shfl_xor_sync(0xffffffffu, s, 2);
                if ((lane & 3) == 0)
                    redsum[wid * 64 + idx] = s;
            }
        __syncthreads();
#pragma unroll
        for (int mt = 0; mt < 4; mt++)
#pragma unroll
            for (int hf = 0; hf < 2; hf++) {
                const int idx = mt * 16 + hf * 8 + rbase;
                inv[mt][hf] = 1.f / (redsum[wid * 64 + idx] +
                                     redsum[(wid ^ 1) * 64 + idx]);
            }
#pragma unroll
        for (int mt = 0; mt < 4; mt++)
#pragma unroll
            for (int nt = 0; nt < 4; nt++) {
                acc[mt][nt][0] *= inv[mt][0]; acc[mt][nt][1] *= inv[mt][0];
                acc[mt][nt][2] *= inv[mt][1]; acc[mt][nt][3] *= inv[mt][1];
            }
    }

    // ---- store (with per-mode row handling) ----
#pragma unroll
    for (int mt = 0; mt < 4; mt++) {
        const int row0 = bm + wm + mt * 16 + (lane >> 2);
        const int row1 = row0 + 8;
        float rm0 = 1.f, rm1 = 1.f;
        bool sub0 = false, sub1 = false;
        if (EPI == 3) {
            rm0 = g_qm[row0] ? 1.f : 0.f;
            rm1 = g_qm[row1] ? 1.f : 0.f;
        }
        if (EPI == 2) {
            sub0 = !g_km[row0];
            sub1 = !g_km[row1];
        }
#pragma unroll
        for (int nt = 0; nt < 4; nt++) {
            const int col = bn + wn + nt * 8 + cl;
            float2 o0, o1;
            o0.x = acc[mt][nt][0] * rm0; o0.y = acc[mt][nt][1] * rm0;
            o1.x = acc[mt][nt][2] * rm1; o1.y = acc[mt][nt][3] * rm1;
            if (EPI == 2) {
                if (sub0) { o0.x = g_khm[col]; o0.y = g_khm[col + 1]; }
                if (sub1) { o1.x = g_khm[col]; o1.y = g_khm[col + 1]; }
            }
            *(float2*)&C[(size_t)row0 * Ee + col] = o0;
            *(float2*)&C[(size_t)row1 * Ee + col] = o1;
        }
    }
}

// =====================================================================
// Mask normalization
// =====================================================================
template<bool QM>
__global__ void norm_mask_kernel(const unsigned char* __restrict__ src, int n)
{
    unsigned char* dst = QM ? g_qm : g_km;
    __shared__ int vote_u8, any_nz;
    if (threadIdx.x == 0) { vote_u8 = 0; any_nz = 0; }
    __syncthreads();
    const unsigned int* w = (const unsigned int*)src;
    const int nw = n >> 2;
    int l_u8 = 0, l_nz = 0;
    for (int i = threadIdx.x; i < nw; i += blockDim.x) {
        unsigned int vv = w[i];
        if (vv != 0u) l_nz = 1;
        if (vv != 0u && vv != 1u && vv != 0x3F800000u) l_u8 = 1;
    }
    if (l_u8) vote_u8 = 1;
    if (l_nz) any_nz = 1;
    __syncthreads();
    if (!any_nz) {
        for (int i = threadIdx.x; i < n; i += blockDim.x) dst[i] = 0;
    } else if (vote_u8) {
        for (int i = threadIdx.x; i < n; i += blockDim.x) dst[i] = src[i] ? 1 : 0;
    } else {
        for (int i = threadIdx.x; i < n; i += blockDim.x) dst[i] = w[i] ? 1 : 0;
    }
}

// =====================================================================
// Exact masked-k-row softmax vector (fp32 one-hot the reference produces)
// =====================================================================
__global__ void khmask_kernel(const float* __restrict__ Wk, const float* __restrict__ bk)
{
    __shared__ float m[Ee];
    const int warp = threadIdx.x >> 5, lane = threadIdx.x & 31;
    for (int r = warp; r < Ee; r += 32) {
        float s = 0.f;
        for (int e = lane; e < Ee; e += 32) s += Wk[(size_t)r * Ee + e];
#pragma unroll
        for (int o = 16; o; o >>= 1) s += __shfl_xor_sync(0xffffffffu, s, o);
        if (lane == 0) m[r] = -1e9f * s + bk[r];
    }
    __syncthreads();
    const int t = threadIdx.x;
    if (t < Hh) {
        float mx = -3.4e38f;
        for (int d = 0; d < Dd; d++) mx = fmaxf(mx, m[t * Dd + d]);
        float sm = 0.f;
        for (int d = 0; d < Dd; d++) sm += expf(m[t * Dd + d] - mx);
        const float inv = 1.f / sm;
        for (int d = 0; d < Dd; d++) g_khm[t * Dd + d] = expf(m[t * Dd + d] - mx) * inv;
    }
}

// zero g_ctx and g_kcum
constexpr int ZTOT = Bb * Hh * Dd * Dd + Bb * Hh * Dd;
__global__ void zero_kernel()
{
    const int i = blockIdx.x * 256 + threadIdx.x;
    if (i < Bb * Hh * Dd * Dd) g_ctx[i] = 0.f;
    else if (i < ZTOT) g_kcum[i - Bb * Hh * Dd * Dd] = 0.f;
}

// =====================================================================
// context[b,h,d,e] += sum_s kh[s,d]*vh[s,e]; folds kcum[d] += kh[s,d].
// =====================================================================
__global__ __launch_bounds__(256) void context_kernel()
{
    const int bh = blockIdx.y;
    const int b = bh >> 4, h = bh & 15;
    const int s0 = blockIdx.x * 256;
    __shared__ __align__(16) float kh[3][16][64];
    __shared__ __align__(16) float vh[3][16][64];

    const int tid  = threadIdx.x;
    const int dB   = (tid >> 4) * 4;
    const int eB   = (tid & 15) * 4;
    const int lrow = tid >> 4;
    const int lseg = tid & 15;
    const uint32_t kB = smem_u32(&kh[0][0][0]);
    const uint32_t vB = smem_u32(&vh[0][0][0]);

    auto issue = [&](int t, int st) {
        const size_t g = ((size_t)(b * Ss + s0 + t * 16 + lrow)) * Ee + h * Dd + lseg * 4;
        CP_ASYNC16(kB + st * 4096 + lrow * 256 + lseg * 16, g_KH + g);
        CP_ASYNC16(vB + st * 4096 + lrow * 256 + lseg * 16, g_VH + g);
        CP_COMMIT();
    };

    float acc[4][4];
#pragma unroll
    for (int i = 0; i < 4; i++)
#pragma unroll
        for (int l = 0; l < 4; l++) acc[i][l] = 0.f;
    float kcp[4] = {0.f, 0.f, 0.f, 0.f};

    issue(0, 0);
    issue(1, 1);
#pragma unroll 1
    for (int t = 0; t < 16; t++) {
        if (t < 15) { CP_WAIT(1); } else { CP_WAIT(0); }
        __syncthreads();
        const int st = t % 3;
#pragma unroll
        for (int j = 0; j < 16; j++) {
            const float4 kv = *(const float4*)&kh[st][j][dB];
            const float4 vv = *(const float4*)&vh[st][j][eB];
            kcp[0] += kv.x; kcp[1] += kv.y; kcp[2] += kv.z; kcp[3] += kv.w;
            acc[0][0] += kv.x * vv.x; acc[0][1] += kv.x * vv.y;
            acc[0][2] += kv.x * vv.z; acc[0][3] += kv.x * vv.w;
            acc[1][0] += kv.y * vv.x; acc[1][1] += kv.y * vv.y;
            acc[1][2] += kv.y * vv.z; acc[1][3] += kv.y * vv.w;
            acc[2][0] += kv.z * vv.x; acc[2][1] += kv.z * vv.y;
            acc[2][2] += kv.z * vv.z; acc[2][3] += kv.z * vv.w;
            acc[3][0] += kv.w * vv.x; acc[3][1] += kv.w * vv.y;
            acc[3][2] += kv.w * vv.z; acc[3][3] += kv.w * vv.w;
        }
        if (t + 2 < 16) issue(t + 2, (t + 2) % 3);
    }

    float* ctx = g_ctx + (size_t)bh * Dd * Dd;
#pragma unroll
    for (int i = 0; i < 4; i++)
#pragma unroll
        for (int l = 0; l < 4; l++)
            atomicAdd(&ctx[(dB + i) * Dd + eB + l], acc[i][l]);
    if ((tid & 15) == 0) {
#pragma unroll
        for (int i = 0; i < 4; i++)
            atomicAdd(&g_kcum[bh * Dd + dB + i], kcp[i]);
    }
}

// out_row = (qh @ ctx) * (1/(qh.kcum)) + qh — emits hi/lo bf16 into g_Ahi/g_Alo
__global__ __launch_bounds__(256) void combine_kernel()
{
    const int bh = blockIdx.y;
    const int b = bh >> 4, h = bh & 15;
    const int s0 = blockIdx.x * 128;
    __shared__ float ctx[64][64];
    __shared__ float kc[64];
    for (int i = threadIdx.x; i < Dd * Dd; i += 256)
        ((float*)ctx)[i] = g_ctx[(size_t)bh * Dd * Dd + i];
    if (threadIdx.x < 64) kc[threadIdx.x] = g_kcum[bh * Dd + threadIdx.x];
    __syncthreads();

    const int warp = threadIdx.x >> 5, lane = threadIdx.x & 31;
    for (int s = s0 + warp; s < s0 + 128; s += 8) {
        const size_t gi = ((size_t)b * Ss + s) * Ee + h * Dd;
        const float* p = g_QH + gi;
        const float q0 = p[lane], q1 = p[lane + 32];
        float dot = q0 * kc[lane] + q1 * kc[lane + 32];
#pragma unroll
        for (int o = 16; o; o >>= 1) dot += __shfl_xor_sync(0xffffffffu, dot, o);
        const float a = 1.f / dot;
        float o0 = 0.f, o1 = 0.f;
#pragma unroll
        for (int d = 0; d < 32; d++) {
            const float qd = __shfl_sync(0xffffffffu, q0, d);
            o0 += qd * ctx[d][lane];
            o1 += qd * ctx[d][lane + 32];
        }
#pragma unroll
        for (int d = 0; d < 32; d++) {
            const float qd = __shfl_sync(0xffffffffu, q1, d);
            o0 += qd * ctx[d + 32][lane];
            o1 += qd * ctx[d + 32][lane + 32];
        }
        const float r0 = o0 * a + q0;
        const float r1 = o1 * a + q1;
        __nv_bfloat16 h0 = __float2bfloat16(r0);
        __nv_bfloat16 h1 = __float2bfloat16(r1);
        g_Ahi[gi + lane]      = h0;
        g_Ahi[gi + lane + 32] = h1;
        g_Alo[gi + lane]      = __float2bfloat16(r0 - __bfloat162float(h0));
        g_Alo[gi + lane + 32] = __float2bfloat16(r1 - __bfloat162float(h1));
    }
}

// =====================================================================
extern "C" void kernel_launch(void* const* d_in, const int* in_sizes, int n_in,
                              void* d_out, int out_size)
{
    const float* q  = (const float*)d_in[0];
    const float* k  = (const float*)d_in[1];
    const float* v  = (const float*)d_in[2];
    const unsigned char* qm_raw = (const unsigned char*)d_in[3];
    const unsigned char* km_raw = (const unsigned char*)d_in[4];
    const float* Wq = (const float*)d_in[5];
    const float* bq = (const float*)d_in[6];
    const float* Wk = (const float*)d_in[7];
    const float* bk = (const float*)d_in[8];
    const float* Wv = (const float*)d_in[9];
    const float* bv = (const float*)d_in[10];
    const float* Wp = (const float*)d_in[11];
    const float* bp = (const float*)d_in[12];
    float* out = (float*)d_out;

    // 0) normalize masks; exact masked-k vector (needed by K GEMM epilogue)
    norm_mask_kernel<true ><<<1, 256>>>(qm_raw, Mtot);
    norm_mask_kernel<false><<<1, 256>>>(km_raw, Mtot);
    khmask_kernel<<<1, 1024>>>(Wk, bk);

    const dim3 gg(Ee / 128, Mtot / 128);   // (8, 128)

    // 1) projections with fused softmax epilogues
    conv_a<1><<<2048, 256>>>(q);  conv_w<<<128, 256>>>(Wq);
    tgemm<1, 0><<<gg, 256>>>(bq, nullptr);            // Q: softmax
    conv_a<2><<<2048, 256>>>(k);  conv_w<<<128, 256>>>(Wk);
    tgemm<2, 1><<<gg, 256>>>(bk, nullptr);            // K: softmax + khm rows
    conv_a<2><<<2048, 256>>>(v);  conv_w<<<128, 256>>>(Wv);
    tgemm<0, 2><<<gg, 256>>>(bv, nullptr);            // V: plain

    // 2) linear-attention core
    zero_kernel<<<(ZTOT + 255) / 256, 256>>>();
    context_kernel<<<dim3(16, Bb * Hh), 256>>>();
    combine_kernel<<<dim3(Ss / 128, Bb * Hh), 256>>>();

    // 3) output projection + output row mask
    conv_w<<<128, 256>>>(Wp);
    tgemm<3, 3><<<gg, 256>>>(bp, out);
}

// round 8
// speedup vs baseline: 2.7476x; 1.6031x over previous
#include <cuda_runtime.h>
#include <cuda_bf16.h>
#include <math.h>
#include <stdint.h>

// ---------------- problem constants ----------------
constexpr int Bb = 4;
constexpr int Ss = 4096;
constexpr int Ee = 1024;
constexpr int Hh = 16;
constexpr int Dd = 64;
constexpr int Mtot = Bb * Ss;          // 16384 rows

// ---------------- scratch (device globals; device-code refs only) ----------------
// QH/KH/VH hold COMPACTED (unmasked-row) data this round.
__device__ __align__(16) float g_QH[(size_t)Mtot * Ee];
__device__ __align__(16) float g_KH[(size_t)Mtot * Ee];
__device__ __align__(16) float g_VH[(size_t)Mtot * Ee];
__device__ __align__(16) float g_ctx[Bb * Hh * Dd * Dd];
__device__ __align__(16) float g_kcum[Bb * Hh * Dd];
__device__ __align__(16) float g_khm[Ee];
__device__ unsigned char g_qm[Mtot];
__device__ unsigned char g_km[Mtot];
__device__ int g_qidx[Mtot];
__device__ int g_kidx[Mtot];
__device__ int g_qoff[5];
__device__ int g_koff[5];
__device__ __align__(16) __nv_bfloat16 g_Ahi[(size_t)Mtot * Ee];
__device__ __align__(16) __nv_bfloat16 g_Alo[(size_t)Mtot * Ee];
__device__ __align__(16) __nv_bfloat16 g_Whi[(size_t)Ee * Ee];
__device__ __align__(16) __nv_bfloat16 g_Wlo[(size_t)Ee * Ee];

// =====================================================================
// helpers
// =====================================================================
__device__ __forceinline__ uint32_t smem_u32(const void* p) {
    uint32_t a;
    asm("{ .reg .u64 t; cvta.to.shared.u64 t, %1; cvt.u32.u64 %0, t; }" : "=r"(a) : "l"(p));
    return a;
}
__device__ __forceinline__ uint32_t sw64(uint32_t off) { return off ^ ((off >> 3) & 0x30); }

#define CP_ASYNC16(dst, src) \
    asm volatile("cp.async.cg.shared.global [%0], [%1], 16;" :: "r"(dst), "l"(src))
#define CP_ASYNC16P(dst, src, sz) \
    asm volatile("cp.async.cg.shared.global [%0], [%1], 16, %2;" :: "r"(dst), "l"(src), "r"(sz))
#define CP_COMMIT() asm volatile("cp.async.commit_group;" ::: "memory")
#define CP_WAIT(N)  asm volatile("cp.async.wait_group %0;" :: "n"(N) : "memory")

#define LDSM4(r, addr)                                                            \
    asm volatile("ldmatrix.sync.aligned.m8n8.x4.shared.b16 {%0,%1,%2,%3}, [%4];"  \
        : "=r"((r)[0]), "=r"((r)[1]), "=r"((r)[2]), "=r"((r)[3]) : "r"(addr))

#define MMA_BF16(d, a, b0, b1)                                                    \
    asm volatile("mma.sync.aligned.m16n8k16.row.col.f32.bf16.bf16.f32 "           \
        "{%0,%1,%2,%3}, {%4,%5,%6,%7}, {%8,%9}, {%0,%1,%2,%3};"                   \
        : "+f"((d)[0]), "+f"((d)[1]), "+f"((d)[2]), "+f"((d)[3])                  \
        : "r"((a)[0]), "r"((a)[1]), "r"((a)[2]), "r"((a)[3]), "r"(b0), "r"(b1))

__device__ __forceinline__ void split4(float4 x, uint2& hv, uint2& lv) {
    __nv_bfloat16 h0 = __float2bfloat16(x.x), h1 = __float2bfloat16(x.y);
    __nv_bfloat16 h2 = __float2bfloat16(x.z), h3 = __float2bfloat16(x.w);
    __nv_bfloat16 l0 = __float2bfloat16(x.x - __bfloat162float(h0));
    __nv_bfloat16 l1 = __float2bfloat16(x.y - __bfloat162float(h1));
    __nv_bfloat16 l2 = __float2bfloat16(x.z - __bfloat162float(h2));
    __nv_bfloat16 l3 = __float2bfloat16(x.w - __bfloat162float(h3));
    __nv_bfloat162 a{h0, h1}, b{h2, h3}, c{l0, l1}, d{l2, l3};
    hv.x = *(uint32_t*)&a; hv.y = *(uint32_t*)&b;
    lv.x = *(uint32_t*)&c; lv.y = *(uint32_t*)&d;
}

// =====================================================================
// Mask normalization (detect bool/int8 vs int32/float32 storage)
// =====================================================================
template<bool QM>
__global__ void norm_mask_kernel(const unsigned char* __restrict__ src, int n)
{
    unsigned char* dst = QM ? g_qm : g_km;
    __shared__ int vote_u8, any_nz;
    if (threadIdx.x == 0) { vote_u8 = 0; any_nz = 0; }
    __syncthreads();
    const unsigned int* w = (const unsigned int*)src;
    const int nw = n >> 2;
    int l_u8 = 0, l_nz = 0;
    for (int i = threadIdx.x; i < nw; i += blockDim.x) {
        unsigned int vv = w[i];
        if (vv != 0u) l_nz = 1;
        if (vv != 0u && vv != 1u && vv != 0x3F800000u) l_u8 = 1;
    }
    if (l_u8) vote_u8 = 1;
    if (l_nz) any_nz = 1;
    __syncthreads();
    if (!any_nz) {
        for (int i = threadIdx.x; i < n; i += blockDim.x) dst[i] = 0;
    } else if (vote_u8) {
        for (int i = threadIdx.x; i < n; i += blockDim.x) dst[i] = src[i] ? 1 : 0;
    } else {
        for (int i = threadIdx.x; i < n; i += blockDim.x) dst[i] = w[i] ? 1 : 0;
    }
}

// =====================================================================
// Deterministic compaction scan: build idx lists + per-batch offsets.
// One block, 256 threads x 64 rows each. Batch boundary = thread 64*b.
// =====================================================================
__global__ void scan_kernel()
{
    __shared__ int qc[256], kc[256], qs[257], ks[257];
    const int t = threadIdx.x;
    int nq = 0, nk = 0;
#pragma unroll 4
    for (int i = 0; i < 64; i++) {
        nq += g_qm[t * 64 + i] ? 1 : 0;
        nk += g_km[t * 64 + i] ? 1 : 0;
    }
    qc[t] = nq; kc[t] = nk;
    __syncthreads();
    if (t == 0) {
        int aq = 0, ak = 0;
        for (int i = 0; i < 256; i++) { qs[i] = aq; ks[i] = ak; aq += qc[i]; ak += kc[i]; }
        qs[256] = aq; ks[256] = ak;
        for (int b = 0; b <= 4; b++) { g_qoff[b] = qs[b * 64]; g_koff[b] = ks[b * 64]; }
    }
    __syncthreads();
    int pq = qs[t], pk = ks[t];
    for (int i = 0; i < 64; i++) {
        const int r = t * 64 + i;
        if (g_qm[r]) g_qidx[pq++] = r;
        if (g_km[r]) g_kidx[pk++] = r;
    }
}

// =====================================================================
// gather + split conversion: unmasked rows only, written compacted.
// LIST: 1 = q-list, 2 = k-list. 8 rows per block.
// =====================================================================
template<int LIST>
__global__ __launch_bounds__(256) void conv_a(const float* __restrict__ src)
{
    const int cnt = (LIST == 1) ? g_qoff[4] : g_koff[4];
    const int ci = blockIdx.x * 8 + (threadIdx.x >> 5);
    if (ci >= cnt) return;
    const int orig = (LIST == 1) ? g_qidx[ci] : g_kidx[ci];
    const int lane = threadIdx.x & 31;
    const float4* s = (const float4*)(src + (size_t)orig * Ee);
    __nv_bfloat16* hi = g_Ahi + (size_t)ci * Ee;
    __nv_bfloat16* lo = g_Alo + (size_t)ci * Ee;
    float4 xs[8];
#pragma unroll
    for (int j = 0; j < 8; j++) xs[j] = s[lane + j * 32];
#pragma unroll
    for (int j = 0; j < 8; j++) {
        uint2 hv, lv;
        split4(xs[j], hv, lv);
        *(uint2*)&hi[(lane + j * 32) * 4] = hv;
        *(uint2*)&lo[(lane + j * 32) * 4] = lv;
    }
}

__global__ __launch_bounds__(256) void conv_w(const float* __restrict__ W)
{
    const size_t base = (size_t)blockIdx.x * 256 + threadIdx.x;
    constexpr size_t stride = 128u * 256u;
    float4 xs[8];
#pragma unroll
    for (int it = 0; it < 8; it++)
        xs[it] = ((const float4*)W)[base + (size_t)it * stride];
#pragma unroll
    for (int it = 0; it < 8; it++) {
        const size_t i4 = base + (size_t)it * stride;
        uint2 hv, lv;
        split4(xs[it], hv, lv);
        *(uint2*)&g_Whi[i4 * 4] = hv;
        *(uint2*)&g_Wlo[i4 * 4] = lv;
    }
}

// =====================================================================
// split-bf16 HMMA GEMM over COMPACTED rows, fused epilogue.
//   EPI: 0 V (+bias, store g_VH), 1 Q (softmax, store g_QH),
//        2 K (softmax, store g_KH), 3 final (+bias, scatter to Cext via qidx).
//   A rows >= cnt are zero-filled (cp.async src-size 0); CTAs past cnt exit.
// =====================================================================
template<int EPI, int DST>
__global__ __launch_bounds__(256, 2) void tgemm(const float* __restrict__ bias,
                                                float* __restrict__ Cext)
{
    const int cnt = (EPI == 1 || EPI == 3) ? g_qoff[4] : g_koff[4];
    const int bm = blockIdx.y * 128;
    if (bm >= cnt) return;

    float* __restrict__ C =
        (DST == 0) ? g_QH : (DST == 1) ? g_KH : (DST == 2) ? g_VH : Cext;

    __shared__ __align__(128) __nv_bfloat16 smA[3][4096];
    __shared__ __align__(128) __nv_bfloat16 smB[3][4096];

    const int tid  = threadIdx.x;
    const int lane = tid & 31;
    const int wid  = tid >> 5;
    const int wm   = (wid >> 2) * 64;
    const int wn   = (wid & 3) * 32;
    const int bn   = blockIdx.x * 128;

    const uint32_t smA0 = smem_u32(&smA[0][0]);
    const uint32_t smB0 = smem_u32(&smB[0][0]);

    const int ldrow = tid >> 1;
    const int ldseg = (tid & 1) * 2;
    const uint32_t asz = (bm + ldrow < cnt) ? 16u : 0u;

    float acc[4][4][4];
#pragma unroll
    for (int mt = 0; mt < 4; mt++)
#pragma unroll
        for (int nt = 0; nt < 4; nt++)
#pragma unroll
            for (int i = 0; i < 4; i++) acc[mt][nt][i] = 0.f;

    auto issue = [&](int s, int st) {
        const int prod = s >> 5;
        const __nv_bfloat16* __restrict__ Ab = (prod == 2) ? g_Alo : g_Ahi;
        const __nv_bfloat16* __restrict__ Bb = (prod == 1) ? g_Wlo : g_Whi;
        const int ks = (s & 31) * 32;
#pragma unroll
        for (int i = 0; i < 2; i++) {
            const int seg = ldseg + i;
            const uint32_t so = sw64((uint32_t)(ldrow * 64 + seg * 16));
            CP_ASYNC16P(smA0 + st * 8192 + so,
                        Ab + (size_t)(bm + ldrow) * Ee + ks + seg * 8, asz);
            CP_ASYNC16(smB0 + st * 8192 + so,
                       Bb + (size_t)(bn + ldrow) * Ee + ks + seg * 8);
        }
        CP_COMMIT();
    };

    issue(0, 0);
    issue(1, 1);

    const int q = lane >> 3, r = lane & 7;

#pragma unroll 1
    for (int s = 0; s < 96; s++) {
        if (s < 95) { CP_WAIT(1); } else { CP_WAIT(0); }
        __syncthreads();
        const int st = s % 3;
        const uint32_t aB = smA0 + st * 8192;
        const uint32_t bB = smB0 + st * 8192;
#pragma unroll
        for (int kk = 0; kk < 32; kk += 16) {
            uint32_t afr[4][4], bfr[2][4];
#pragma unroll
            for (int mt = 0; mt < 4; mt++) {
                const int row = wm + mt * 16 + (q & 1) * 8 + r;
                LDSM4(afr[mt], aB + sw64((uint32_t)(row * 64 + kk * 2 + (q >> 1) * 16)));
            }
            {
                const int rowb = wn + q * 8 + r;
                LDSM4(bfr[0], bB + sw64((uint32_t)(rowb * 64 + kk * 2)));
                LDSM4(bfr[1], bB + sw64((uint32_t)(rowb * 64 + kk * 2 + 16)));
            }
#pragma unroll
            for (int mt = 0; mt < 4; mt++)
#pragma unroll
                for (int nt = 0; nt < 4; nt++)
                    MMA_BF16(acc[mt][nt], afr[mt], bfr[0][nt], bfr[1][nt]);
        }
        if (s + 2 < 96) issue(s + 2, (s + 2) % 3);
    }

    // ================= epilogue =================
    __syncthreads();

    const int cl = 2 * (lane & 3);
#pragma unroll
    for (int nt = 0; nt < 4; nt++) {
        const float2 bb = *(const float2*)&bias[bn + wn + nt * 8 + cl];
#pragma unroll
        for (int mt = 0; mt < 4; mt++) {
            acc[mt][nt][0] += bb.x; acc[mt][nt][1] += bb.y;
            acc[mt][nt][2] += bb.x; acc[mt][nt][3] += bb.y;
        }
    }

    if (EPI == 1 || EPI == 2) {
        float* redmax = (float*)&smA[0][0];
        float* redsum = redmax + 512;
        const int rbase = (lane >> 2);
        float inv[4][2];
#pragma unroll
        for (int mt = 0; mt < 4; mt++)
#pragma unroll
            for (int hf = 0; hf < 2; hf++) {
                float m = -3.4e38f;
#pragma unroll
                for (int nt = 0; nt < 4; nt++)
                    m = fmaxf(m, fmaxf(acc[mt][nt][2 * hf], acc[mt][nt][2 * hf + 1]));
                m = fmaxf(m, __shfl_xor_sync(0xffffffffu, m, 1));
                m = fmaxf(m, __shfl_xor_sync(0xffffffffu, m, 2));
                if ((lane & 3) == 0)
                    redmax[wid * 64 + mt * 16 + hf * 8 + rbase] = m;
            }
        __syncthreads();
#pragma unroll
        for (int mt = 0; mt < 4; mt++)
#pragma unroll
            for (int hf = 0; hf < 2; hf++) {
                const int idx = mt * 16 + hf * 8 + rbase;
                const float rm = fmaxf(redmax[wid * 64 + idx],
                                       redmax[(wid ^ 1) * 64 + idx]);
                float s = 0.f;
#pragma unroll
                for (int nt = 0; nt < 4; nt++) {
                    float a0 = __expf(acc[mt][nt][2 * hf]     - rm);
                    float a1 = __expf(acc[mt][nt][2 * hf + 1] - rm);
                    acc[mt][nt][2 * hf] = a0; acc[mt][nt][2 * hf + 1] = a1;
                    s += a0 + a1;
                }
                s += __shfl_xor_sync(0xffffffffu, s, 1);
                s += __shfl_xor_sync(0xffffffffu, s, 2);
                if ((lane & 3) == 0)
                    redsum[wid * 64 + idx] = s;
            }
        __syncthreads();
#pragma unroll
        for (int mt = 0; mt < 4; mt++)
#pragma unroll
            for (int hf = 0; hf < 2; hf++) {
                const int idx = mt * 16 + hf * 8 + rbase;
                inv[mt][hf] = 1.f / (redsum[wid * 64 + idx] +
                                     redsum[(wid ^ 1) * 64 + idx]);
            }
#pragma unroll
        for (int mt = 0; mt < 4; mt++)
#pragma unroll
            for (int nt = 0; nt < 4; nt++) {
                acc[mt][nt][0] *= inv[mt][0]; acc[mt][nt][1] *= inv[mt][0];
                acc[mt][nt][2] *= inv[mt][1]; acc[mt][nt][3] *= inv[mt][1];
            }
    }

    // ---- store (compact rows < cnt only; EPI3 scatters via qidx) ----
#pragma unroll
    for (int mt = 0; mt < 4; mt++) {
        const int row0 = bm + wm + mt * 16 + (lane >> 2);
        const int row1 = row0 + 8;
#pragma unroll
        for (int nt = 0; nt < 4; nt++) {
            const int col = bn + wn + nt * 8 + cl;
            float2 o0{acc[mt][nt][0], acc[mt][nt][1]};
            float2 o1{acc[mt][nt][2], acc[mt][nt][3]};
            if (EPI == 3) {
                if (row0 < cnt) *(float2*)&C[(size_t)g_qidx[row0] * Ee + col] = o0;
                if (row1 < cnt) *(float2*)&C[(size_t)g_qidx[row1] * Ee + col] = o1;
            } else {
                if (row0 < cnt) *(float2*)&C[(size_t)row0 * Ee + col] = o0;
                if (row1 < cnt) *(float2*)&C[(size_t)row1 * Ee + col] = o1;
            }
        }
    }
}

// =====================================================================
// Exact masked-k-row softmax vector (fp32 one-hot the reference produces)
// =====================================================================
__global__ void khmask_kernel(const float* __restrict__ Wk, const float* __restrict__ bk)
{
    __shared__ float m[Ee];
    const int warp = threadIdx.x >> 5, lane = threadIdx.x & 31;
    for (int r = warp; r < Ee; r += 32) {
        float s = 0.f;
        for (int e = lane; e < Ee; e += 32) s += Wk[(size_t)r * Ee + e];
#pragma unroll
        for (int o = 16; o; o >>= 1) s += __shfl_xor_sync(0xffffffffu, s, o);
        if (lane == 0) m[r] = -1e9f * s + bk[r];
    }
    __syncthreads();
    const int t = threadIdx.x;
    if (t < Hh) {
        float mx = -3.4e38f;
        for (int d = 0; d < Dd; d++) mx = fmaxf(mx, m[t * Dd + d]);
        float sm = 0.f;
        for (int d = 0; d < Dd; d++) sm += expf(m[t * Dd + d] - mx);
        const float inv = 1.f / sm;
        for (int d = 0; d < Dd; d++) g_khm[t * Dd + d] = expf(m[t * Dd + d] - mx) * inv;
    }
}

// =====================================================================
// init ctx/kcum with analytic masked-row corrections:
//   ctx[b,h] = n_masked * khm_h (x) bv_h ; kcum[b,h] = n_masked * khm_h
// =====================================================================
__global__ void init_ctx(const float* __restrict__ bv)
{
    const int bh = blockIdx.x;
    const int b = bh >> 4, h = bh & 15;
    const float nm = (float)(Ss - (g_koff[b + 1] - g_koff[b]));
    for (int i = threadIdx.x; i < Dd * Dd; i += 256) {
        const int d = i >> 6, e = i & 63;
        g_ctx[bh * Dd * Dd + i] = nm * g_khm[h * Dd + d] * bv[h * Dd + e];
    }
    if (threadIdx.x < 64)
        g_kcum[bh * Dd + threadIdx.x] = nm * g_khm[h * Dd + threadIdx.x];
}

// =====================================================================
// context over compacted per-batch segment; folds kcum.
// =====================================================================
__global__ __launch_bounds__(256) void context_kernel()
{
    const int bh = blockIdx.y;
    const int b = bh >> 4, h = bh & 15;
    const int base = g_koff[b];
    const int cntb = g_koff[b + 1] - base;
    const int s0 = blockIdx.x * 256;
    if (s0 >= cntb) return;

    __shared__ __align__(16) float kh[3][16][64];
    __shared__ __align__(16) float vh[3][16][64];

    const int tid  = threadIdx.x;
    const int dB   = (tid >> 4) * 4;
    const int eB   = (tid & 15) * 4;
    const int lrow = tid >> 4;
    const int lseg = tid & 15;
    const uint32_t kB = smem_u32(&kh[0][0][0]);
    const uint32_t vB = smem_u32(&vh[0][0][0]);

    auto issue = [&](int t, int st) {
        const int row = s0 + t * 16 + lrow;
        const uint32_t sz = (row < cntb) ? 16u : 0u;
        const int rc = (row < cntb) ? row : 0;
        const size_t g = ((size_t)(base + rc)) * Ee + h * Dd + lseg * 4;
        CP_ASYNC16P(kB + st * 4096 + lrow * 256 + lseg * 16, g_KH + g, sz);
        CP_ASYNC16P(vB + st * 4096 + lrow * 256 + lseg * 16, g_VH + g, sz);
        CP_COMMIT();
    };

    float acc[4][4];
#pragma unroll
    for (int i = 0; i < 4; i++)
#pragma unroll
        for (int l = 0; l < 4; l++) acc[i][l] = 0.f;
    float kcp[4] = {0.f, 0.f, 0.f, 0.f};

    issue(0, 0);
    issue(1, 1);
#pragma unroll 1
    for (int t = 0; t < 16; t++) {
        if (t < 15) { CP_WAIT(1); } else { CP_WAIT(0); }
        __syncthreads();
        const int st = t % 3;
#pragma unroll
        for (int j = 0; j < 16; j++) {
            const float4 kv = *(const float4*)&kh[st][j][dB];
            const float4 vv = *(const float4*)&vh[st][j][eB];
            kcp[0] += kv.x; kcp[1] += kv.y; kcp[2] += kv.z; kcp[3] += kv.w;
            acc[0][0] += kv.x * vv.x; acc[0][1] += kv.x * vv.y;
            acc[0][2] += kv.x * vv.z; acc[0][3] += kv.x * vv.w;
            acc[1][0] += kv.y * vv.x; acc[1][1] += kv.y * vv.y;
            acc[1][2] += kv.y * vv.z; acc[1][3] += kv.y * vv.w;
            acc[2][0] += kv.z * vv.x; acc[2][1] += kv.z * vv.y;
            acc[2][2] += kv.z * vv.z; acc[2][3] += kv.z * vv.w;
            acc[3][0] += kv.w * vv.x; acc[3][1] += kv.w * vv.y;
            acc[3][2] += kv.w * vv.z; acc[3][3] += kv.w * vv.w;
        }
        if (t + 2 < 16) issue(t + 2, (t + 2) % 3);
    }

    float* ctx = g_ctx + (size_t)bh * Dd * Dd;
#pragma unroll
    for (int i = 0; i < 4; i++)
#pragma unroll
        for (int l = 0; l < 4; l++)
            atomicAdd(&ctx[(dB + i) * Dd + eB + l], acc[i][l]);
    if ((tid & 15) == 0) {
#pragma unroll
        for (int i = 0; i < 4; i++)
            atomicAdd(&g_kcum[bh * Dd + dB + i], kcp[i]);
    }
}

// =====================================================================
// combine over compacted q rows; emits hi/lo bf16 at compact positions.
// =====================================================================
__global__ __launch_bounds__(256) void combine_kernel()
{
    const int bh = blockIdx.y;
    const int b = bh >> 4, h = bh & 15;
    const int base = g_qoff[b];
    const int cntb = g_qoff[b + 1] - base;
    const int s0 = blockIdx.x * 128;
    if (s0 >= cntb) return;

    __shared__ float ctx[64][64];
    __shared__ float kc[64];
    for (int i = threadIdx.x; i < Dd * Dd; i += 256)
        ((float*)ctx)[i] = g_ctx[(size_t)bh * Dd * Dd + i];
    if (threadIdx.x < 64) kc[threadIdx.x] = g_kcum[bh * Dd + threadIdx.x];
    __syncthreads();

    const int warp = threadIdx.x >> 5, lane = threadIdx.x & 31;
    const int lim = (s0 + 128 < cntb) ? (s0 + 128) : cntb;
    for (int s = s0 + warp; s < lim; s += 8) {
        const size_t gi = ((size_t)(base + s)) * Ee + h * Dd;
        const float* p = g_QH + gi;
        const float q0 = p[lane], q1 = p[lane + 32];
        float dot = q0 * kc[lane] + q1 * kc[lane + 32];
#pragma unroll
        for (int o = 16; o; o >>= 1) dot += __shfl_xor_sync(0xffffffffu, dot, o);
        const float a = 1.f / dot;
        float o0 = 0.f, o1 = 0.f;
#pragma unroll
        for (int d = 0; d < 32; d++) {
            const float qd = __shfl_sync(0xffffffffu, q0, d);
            o0 += qd * ctx[d][lane];
            o1 += qd * ctx[d][lane + 32];
        }
#pragma unroll
        for (int d = 0; d < 32; d++) {
            const float qd = __shfl_sync(0xffffffffu, q1, d);
            o0 += qd * ctx[d + 32][lane];
            o1 += qd * ctx[d + 32][lane + 32];
        }
        const float r0 = o0 * a + q0;
        const float r1 = o1 * a + q1;
        __nv_bfloat16 h0 = __float2bfloat16(r0);
        __nv_bfloat16 h1 = __float2bfloat16(r1);
        g_Ahi[gi + lane]      = h0;
        g_Ahi[gi + lane + 32] = h1;
        g_Alo[gi + lane]      = __float2bfloat16(r0 - __bfloat162float(h0));
        g_Alo[gi + lane + 32] = __float2bfloat16(r1 - __bfloat162float(h1));
    }
}

// zero masked output rows (unmasked rows are written by the final GEMM)
__global__ __launch_bounds__(256) void zero_out_kernel(float* __restrict__ out)
{
    const int row = blockIdx.x * 8 + (threadIdx.x >> 5);
    if (g_qm[row]) return;
    const int lane = threadIdx.x & 31;
    const float4 z{0.f, 0.f, 0.f, 0.f};
    float4* o = (float4*)(out + (size_t)row * Ee);
#pragma unroll
    for (int j = 0; j < 8; j++) o[lane + j * 32] = z;
}

// =====================================================================
extern "C" void kernel_launch(void* const* d_in, const int* in_sizes, int n_in,
                              void* d_out, int out_size)
{
    const float* q  = (const float*)d_in[0];
    const float* k  = (const float*)d_in[1];
    const float* v  = (const float*)d_in[2];
    const unsigned char* qm_raw = (const unsigned char*)d_in[3];
    const unsigned char* km_raw = (const unsigned char*)d_in[4];
    const float* Wq = (const float*)d_in[5];
    const float* bq = (const float*)d_in[6];
    const float* Wk = (const float*)d_in[7];
    const float* bk = (const float*)d_in[8];
    const float* Wv = (const float*)d_in[9];
    const float* bv = (const float*)d_in[10];
    const float* Wp = (const float*)d_in[11];
    const float* bp = (const float*)d_in[12];
    float* out = (float*)d_out;

    // 0) masks -> compaction lists; exact masked-k vector
    norm_mask_kernel<true ><<<1, 256>>>(qm_raw, Mtot);
    norm_mask_kernel<false><<<1, 256>>>(km_raw, Mtot);
    scan_kernel<<<1, 256>>>();
    khmask_kernel<<<1, 1024>>>(Wk, bk);

    const dim3 gg(Ee / 128, Mtot / 128);   // worst-case grid; CTAs past cnt exit

    // 1) projections over compacted rows, fused softmax epilogues
    conv_a<1><<<2048, 256>>>(q);  conv_w<<<128, 256>>>(Wq);
    tgemm<1, 0><<<gg, 256>>>(bq, nullptr);            // Q: softmax -> g_QH (compact)
    conv_a<2><<<2048, 256>>>(k);  conv_w<<<128, 256>>>(Wk);
    tgemm<2, 1><<<gg, 256>>>(bk, nullptr);            // K: softmax -> g_KH (compact)
    conv_a<2><<<2048, 256>>>(v);  conv_w<<<128, 256>>>(Wv);
    tgemm<0, 2><<<gg, 256>>>(bv, nullptr);            // V: plain  -> g_VH (compact)

    // 2) linear-attention core with analytic masked-row corrections
    init_ctx<<<Bb * Hh, 256>>>(bv);
    context_kernel<<<dim3(16, Bb * Hh), 256>>>();
    combine_kernel<<<dim3(32, Bb * Hh), 256>>>();

    // 3) output projection: zero masked rows, scatter unmasked rows
    conv_w<<<128, 256>>>(Wp);
    zero_out_kernel<<<2048, 256>>>(out);
    tgemm<3, 3><<<gg, 256>>>(bp, out);
}

// round 9
// speedup vs baseline: 3.0671x; 1.1163x over previous
#include <cuda_runtime.h>
#include <cuda_bf16.h>
#include <math.h>
#include <stdint.h>

// ---------------- problem constants ----------------
constexpr int Bb = 4;
constexpr int Ss = 4096;
constexpr int Ee = 1024;
constexpr int Hh = 16;
constexpr int Dd = 64;
constexpr int Mtot = Bb * Ss;

// ---------------- scratch (device globals; device-code refs only) ----------------
__device__ __align__(16) float g_QH[(size_t)Mtot * Ee];
__device__ __align__(16) float g_KH[(size_t)Mtot * Ee];
__device__ __align__(16) float g_VH[(size_t)Mtot * Ee];
__device__ __align__(16) float g_ctx[Bb * Hh * Dd * Dd];
__device__ __align__(16) float g_kcum[Bb * Hh * Dd];
__device__ __align__(16) float g_khm[Ee];
__device__ __align__(16) float g_mvec[Ee];
__device__ unsigned char g_qm[Mtot];
__device__ unsigned char g_km[Mtot];
__device__ int g_qidx[Mtot];
__device__ int g_kidx[Mtot];
__device__ int g_qoff[5];
__device__ int g_koff[5];
// per-input split-bf16 operand buffers (compact rows)
__device__ __align__(16) __nv_bfloat16 g_Qhi[(size_t)Mtot * Ee];
__device__ __align__(16) __nv_bfloat16 g_Qlo[(size_t)Mtot * Ee];
__device__ __align__(16) __nv_bfloat16 g_Khi[(size_t)Mtot * Ee];
__device__ __align__(16) __nv_bfloat16 g_Klo[(size_t)Mtot * Ee];
__device__ __align__(16) __nv_bfloat16 g_Vhi[(size_t)Mtot * Ee];
__device__ __align__(16) __nv_bfloat16 g_Vlo[(size_t)Mtot * Ee];
__device__ __align__(16) __nv_bfloat16 g_Wqhi[(size_t)Ee * Ee];
__device__ __align__(16) __nv_bfloat16 g_Wqlo[(size_t)Ee * Ee];
__device__ __align__(16) __nv_bfloat16 g_Wkhi[(size_t)Ee * Ee];
__device__ __align__(16) __nv_bfloat16 g_Wklo[(size_t)Ee * Ee];
__device__ __align__(16) __nv_bfloat16 g_Wvhi[(size_t)Ee * Ee];
__device__ __align__(16) __nv_bfloat16 g_Wvlo[(size_t)Ee * Ee];

// =====================================================================
// helpers
// =====================================================================
__device__ __forceinline__ uint32_t smem_u32(const void* p) {
    uint32_t a;
    asm("{ .reg .u64 t; cvta.to.shared.u64 t, %1; cvt.u32.u64 %0, t; }" : "=r"(a) : "l"(p));
    return a;
}
__device__ __forceinline__ uint32_t sw64(uint32_t off) { return off ^ ((off >> 3) & 0x30); }

#define CP_ASYNC16(dst, src) \
    asm volatile("cp.async.cg.shared.global [%0], [%1], 16;" :: "r"(dst), "l"(src))
#define CP_ASYNC16P(dst, src, sz) \
    asm volatile("cp.async.cg.shared.global [%0], [%1], 16, %2;" :: "r"(dst), "l"(src), "r"(sz))
#define CP_COMMIT() asm volatile("cp.async.commit_group;" ::: "memory")
#define CP_WAIT(N)  asm volatile("cp.async.wait_group %0;" :: "n"(N) : "memory")

#define LDSM4(r, addr)                                                            \
    asm volatile("ldmatrix.sync.aligned.m8n8.x4.shared.b16 {%0,%1,%2,%3}, [%4];"  \
        : "=r"((r)[0]), "=r"((r)[1]), "=r"((r)[2]), "=r"((r)[3]) : "r"(addr))

#define MMA_BF16(d, a, b0, b1)                                                    \
    asm volatile("mma.sync.aligned.m16n8k16.row.col.f32.bf16.bf16.f32 "           \
        "{%0,%1,%2,%3}, {%4,%5,%6,%7}, {%8,%9}, {%0,%1,%2,%3};"                   \
        : "+f"((d)[0]), "+f"((d)[1]), "+f"((d)[2]), "+f"((d)[3])                  \
        : "r"((a)[0]), "r"((a)[1]), "r"((a)[2]), "r"((a)[3]), "r"(b0), "r"(b1))

__device__ __forceinline__ void split4(float4 x, uint2& hv, uint2& lv) {
    __nv_bfloat16 h0 = __float2bfloat16(x.x), h1 = __float2bfloat16(x.y);
    __nv_bfloat16 h2 = __float2bfloat16(x.z), h3 = __float2bfloat16(x.w);
    __nv_bfloat16 l0 = __float2bfloat16(x.x - __bfloat162float(h0));
    __nv_bfloat16 l1 = __float2bfloat16(x.y - __bfloat162float(h1));
    __nv_bfloat16 l2 = __float2bfloat16(x.z - __bfloat162float(h2));
    __nv_bfloat16 l3 = __float2bfloat16(x.w - __bfloat162float(h3));
    __nv_bfloat162 a{h0, h1}, b{h2, h3}, c{l0, l1}, d{l2, l3};
    hv.x = *(uint32_t*)&a; hv.y = *(uint32_t*)&b;
    lv.x = *(uint32_t*)&c; lv.y = *(uint32_t*)&d;
}

// =====================================================================
// Mask normalization (detect bool/int8 vs int32/float32 storage)
// =====================================================================
template<bool QM>
__global__ void norm_mask_kernel(const unsigned char* __restrict__ src, int n)
{
    unsigned char* dst = QM ? g_qm : g_km;
    __shared__ int vote_u8, any_nz;
    if (threadIdx.x == 0) { vote_u8 = 0; any_nz = 0; }
    __syncthreads();
    const unsigned int* w = (const unsigned int*)src;
    const int nw = n >> 2;
    int l_u8 = 0, l_nz = 0;
    for (int i = threadIdx.x; i < nw; i += blockDim.x) {
        unsigned int vv = w[i];
        if (vv != 0u) l_nz = 1;
        if (vv != 0u && vv != 1u && vv != 0x3F800000u) l_u8 = 1;
    }
    if (l_u8) vote_u8 = 1;
    if (l_nz) any_nz = 1;
    __syncthreads();
    if (!any_nz) {
        for (int i = threadIdx.x; i < n; i += blockDim.x) dst[i] = 0;
    } else if (vote_u8) {
        for (int i = threadIdx.x; i < n; i += blockDim.x) dst[i] = src[i] ? 1 : 0;
    } else {
        for (int i = threadIdx.x; i < n; i += blockDim.x) dst[i] = w[i] ? 1 : 0;
    }
}

// =====================================================================
// Deterministic compaction scan
// =====================================================================
__global__ void scan_kernel()
{
    __shared__ int qc[256], kc[256], qs[257], ks[257];
    const int t = threadIdx.x;
    int nq = 0, nk = 0;
#pragma unroll 4
    for (int i = 0; i < 64; i++) {
        nq += g_qm[t * 64 + i] ? 1 : 0;
        nk += g_km[t * 64 + i] ? 1 : 0;
    }
    qc[t] = nq; kc[t] = nk;
    __syncthreads();
    if (t == 0) {
        int aq = 0, ak = 0;
        for (int i = 0; i < 256; i++) { qs[i] = aq; ks[i] = ak; aq += qc[i]; ak += kc[i]; }
        qs[256] = aq; ks[256] = ak;
        for (int b = 0; b <= 4; b++) { g_qoff[b] = qs[b * 64]; g_koff[b] = ks[b * 64]; }
    }
    __syncthreads();
    int pq = qs[t], pk = ks[t];
    for (int i = 0; i < 64; i++) {
        const int r = t * 64 + i;
        if (g_qm[r]) g_qidx[pq++] = r;
        if (g_km[r]) g_kidx[pk++] = r;
    }
}

// =====================================================================
// khmask stage 1: parallel rowsums (warp per row, same lane-stride order)
// =====================================================================
__global__ __launch_bounds__(256) void khmask1_kernel(const float* __restrict__ Wk,
                                                      const float* __restrict__ bk)
{
    const int r = blockIdx.x * 8 + (threadIdx.x >> 5);
    const int lane = threadIdx.x & 31;
    float s = 0.f;
    for (int e = lane; e < Ee; e += 32) s += Wk[(size_t)r * Ee + e];
#pragma unroll
    for (int o = 16; o; o >>= 1) s += __shfl_xor_sync(0xffffffffu, s, o);
    if (lane == 0) g_mvec[r] = -1e9f * s + bk[r];
}

// khmask stage 2: exact per-head softmax of g_mvec (serial per head, as before)
__global__ void khmask2_kernel()
{
    const int t = threadIdx.x;
    if (t < Hh) {
        float mx = -3.4e38f;
        for (int d = 0; d < Dd; d++) mx = fmaxf(mx, g_mvec[t * Dd + d]);
        float sm = 0.f;
        for (int d = 0; d < Dd; d++) sm += expf(g_mvec[t * Dd + d] - mx);
        const float inv = 1.f / sm;
        for (int d = 0; d < Dd; d++) g_khm[t * Dd + d] = expf(g_mvec[t * Dd + d] - mx) * inv;
    }
}

// =====================================================================
// batched gather + split conversion: z=0 q-list<-q, z=1 k-list<-k, z=2 k-list<-v
// =====================================================================
__global__ __launch_bounds__(256) void conv_a3(const float* __restrict__ q,
                                               const float* __restrict__ k,
                                               const float* __restrict__ v)
{
    const int z = blockIdx.y;
    const int cnt = (z == 0) ? g_qoff[4] : g_koff[4];
    const int ci = blockIdx.x * 8 + (threadIdx.x >> 5);
    if (ci >= cnt) return;
    const int orig = (z == 0) ? g_qidx[ci] : g_kidx[ci];
    const float* __restrict__ src = (z == 0) ? q : (z == 1) ? k : v;
    __nv_bfloat16* hi = (z == 0) ? g_Qhi : (z == 1) ? g_Khi : g_Vhi;
    __nv_bfloat16* lo = (z == 0) ? g_Qlo : (z == 1) ? g_Klo : g_Vlo;
    const int lane = threadIdx.x & 31;
    const float4* s = (const float4*)(src + (size_t)orig * Ee);
    hi += (size_t)ci * Ee;
    lo += (size_t)ci * Ee;
    float4 xs[8];
#pragma unroll
    for (int j = 0; j < 8; j++) xs[j] = s[lane + j * 32];
#pragma unroll
    for (int j = 0; j < 8; j++) {
        uint2 hv, lv;
        split4(xs[j], hv, lv);
        *(uint2*)&hi[(lane + j * 32) * 4] = hv;
        *(uint2*)&lo[(lane + j * 32) * 4] = lv;
    }
}

// batched W conversion: z selects (Wq, Wk, Wv)
__global__ __launch_bounds__(256) void conv_w3(const float* __restrict__ Wq,
                                               const float* __restrict__ Wk,
                                               const float* __restrict__ Wv)
{
    const int z = blockIdx.y;
    const float* __restrict__ W = (z == 0) ? Wq : (z == 1) ? Wk : Wv;
    __nv_bfloat16* hi = (z == 0) ? g_Wqhi : (z == 1) ? g_Wkhi : g_Wvhi;
    __nv_bfloat16* lo = (z == 0) ? g_Wqlo : (z == 1) ? g_Wklo : g_Wvlo;
    const size_t base = (size_t)blockIdx.x * 256 + threadIdx.x;
    constexpr size_t stride = 128u * 256u;
    float4 xs[8];
#pragma unroll
    for (int it = 0; it < 8; it++)
        xs[it] = ((const float4*)W)[base + (size_t)it * stride];
#pragma unroll
    for (int it = 0; it < 8; it++) {
        const size_t i4 = base + (size_t)it * stride;
        uint2 hv, lv;
        split4(xs[it], hv, lv);
        *(uint2*)&hi[i4 * 4] = hv;
        *(uint2*)&lo[i4 * 4] = lv;
    }
}

// single W conversion for Wp (into g_Wqhi/g_Wqlo, reused)
__global__ __launch_bounds__(256) void conv_w1(const float* __restrict__ W)
{
    const size_t base = (size_t)blockIdx.x * 256 + threadIdx.x;
    constexpr size_t stride = 128u * 256u;
    float4 xs[8];
#pragma unroll
    for (int it = 0; it < 8; it++)
        xs[it] = ((const float4*)W)[base + (size_t)it * stride];
#pragma unroll
    for (int it = 0; it < 8; it++) {
        const size_t i4 = base + (size_t)it * stride;
        uint2 hv, lv;
        split4(xs[it], hv, lv);
        *(uint2*)&g_Wqhi[i4 * 4] = hv;
        *(uint2*)&g_Wqlo[i4 * 4] = lv;
    }
}

// =====================================================================
// GEMM mainloop+epilogue shared body (device inline).
//   dosm: softmax epilogue; dokhm: masked-row khm substitution;
//   scatter: store rows via g_qidx (final GEMM).
// =====================================================================
__device__ __forceinline__ void gemm_body(
    const __nv_bfloat16* __restrict__ Ahi, const __nv_bfloat16* __restrict__ Alo,
    const __nv_bfloat16* __restrict__ Bhi, const __nv_bfloat16* __restrict__ Blo,
    const float* __restrict__ bias, float* __restrict__ C,
    int cnt, int bm, int bn, bool dosm, bool dokhm, bool scatter,
    char* smraw)
{
    __nv_bfloat16* smA = (__nv_bfloat16*)smraw;            // 3 x 8KB
    __nv_bfloat16* smB = (__nv_bfloat16*)(smraw + 24576);  // 3 x 8KB

    const int tid  = threadIdx.x;
    const int lane = tid & 31;
    const int wid  = tid >> 5;
    const int wm   = (wid >> 2) * 64;
    const int wn   = (wid & 3) * 32;

    const uint32_t smA0 = smem_u32(smA);
    const uint32_t smB0 = smem_u32(smB);

    const int ldrow = tid >> 1;
    const int ldseg = (tid & 1) * 2;
    const uint32_t asz = (bm + ldrow < cnt) ? 16u : 0u;

    float acc[4][4][4];
#pragma unroll
    for (int mt = 0; mt < 4; mt++)
#pragma unroll
        for (int nt = 0; nt < 4; nt++)
#pragma unroll
            for (int i = 0; i < 4; i++) acc[mt][nt][i] = 0.f;

    auto issue = [&](int s, int st) {
        const int prod = s >> 5;
        const __nv_bfloat16* __restrict__ Ab = (prod == 2) ? Alo : Ahi;
        const __nv_bfloat16* __restrict__ Bb = (prod == 1) ? Blo : Bhi;
        const int ks = (s & 31) * 32;
#pragma unroll
        for (int i = 0; i < 2; i++) {
            const int seg = ldseg + i;
            const uint32_t so = sw64((uint32_t)(ldrow * 64 + seg * 16));
            CP_ASYNC16P(smA0 + st * 8192 + so,
                        Ab + (size_t)(bm + ldrow) * Ee + ks + seg * 8, asz);
            CP_ASYNC16(smB0 + st * 8192 + so,
                       Bb + (size_t)(bn + ldrow) * Ee + ks + seg * 8);
        }
        CP_COMMIT();
    };

    issue(0, 0);
    issue(1, 1);

    const int q = lane >> 3, r = lane & 7;

#pragma unroll 1
    for (int s = 0; s < 96; s++) {
        if (s < 95) { CP_WAIT(1); } else { CP_WAIT(0); }
        __syncthreads();
        const int st = s % 3;
        const uint32_t aB = smA0 + st * 8192;
        const uint32_t bB = smB0 + st * 8192;
#pragma unroll
        for (int kk = 0; kk < 32; kk += 16) {
            uint32_t afr[4][4], bfr[2][4];
#pragma unroll
            for (int mt = 0; mt < 4; mt++) {
                const int row = wm + mt * 16 + (q & 1) * 8 + r;
                LDSM4(afr[mt], aB + sw64((uint32_t)(row * 64 + kk * 2 + (q >> 1) * 16)));
            }
            {
                const int rowb = wn + q * 8 + r;
                LDSM4(bfr[0], bB + sw64((uint32_t)(rowb * 64 + kk * 2)));
                LDSM4(bfr[1], bB + sw64((uint32_t)(rowb * 64 + kk * 2 + 16)));
            }
#pragma unroll
            for (int mt = 0; mt < 4; mt++)
#pragma unroll
                for (int nt = 0; nt < 4; nt++)
                    MMA_BF16(acc[mt][nt], afr[mt], bfr[0][nt], bfr[1][nt]);
        }
        if (s + 2 < 96) issue(s + 2, (s + 2) % 3);
    }

    // ---- epilogue ----
    __syncthreads();

    const int cl = 2 * (lane & 3);
#pragma unroll
    for (int nt = 0; nt < 4; nt++) {
        const float2 bb = *(const float2*)&bias[bn + wn + nt * 8 + cl];
#pragma unroll
        for (int mt = 0; mt < 4; mt++) {
            acc[mt][nt][0] += bb.x; acc[mt][nt][1] += bb.y;
            acc[mt][nt][2] += bb.x; acc[mt][nt][3] += bb.y;
        }
    }

    if (dosm) {
        float* redmax = (float*)smA;
        float* redsum = redmax + 512;
        const int rbase = (lane >> 2);
        float inv[4][2];
#pragma unroll
        for (int mt = 0; mt < 4; mt++)
#pragma unroll
            for (int hf = 0; hf < 2; hf++) {
                float m = -3.4e38f;
#pragma unroll
                for (int nt = 0; nt < 4; nt++)
                    m = fmaxf(m, fmaxf(acc[mt][nt][2 * hf], acc[mt][nt][2 * hf + 1]));
                m = fmaxf(m, __shfl_xor_sync(0xffffffffu, m, 1));
                m = fmaxf(m, __shfl_xor_sync(0xffffffffu, m, 2));
                if ((lane & 3) == 0)
                    redmax[wid * 64 + mt * 16 + hf * 8 + rbase] = m;
            }
        __syncthreads();
#pragma unroll
        for (int mt = 0; mt < 4; mt++)
#pragma unroll
            for (int hf = 0; hf < 2; hf++) {
                const int idx = mt * 16 + hf * 8 + rbase;
                const float rm = fmaxf(redmax[wid * 64 + idx],
                                       redmax[(wid ^ 1) * 64 + idx]);
                float s = 0.f;
#pragma unroll
                for (int nt = 0; nt < 4; nt++) {
                    float a0 = __expf(acc[mt][nt][2 * hf]     - rm);
                    float a1 = __expf(acc[mt][nt][2 * hf + 1] - rm);
                    acc[mt][nt][2 * hf] = a0; acc[mt][nt][2 * hf + 1] = a1;
                    s += a0 + a1;
                }
                s += __shfl_xor_sync(0xffffffffu, s, 1);
                s += __shfl_xor_sync(0xffffffffu, s, 2);
                if ((lane & 3) == 0)
                    redsum[wid * 64 + idx] = s;
            }
        __syncthreads();
#pragma unroll
        for (int mt = 0; mt < 4; mt++)
#pragma unroll
            for (int hf = 0; hf < 2; hf++) {
                const int idx = mt * 16 + hf * 8 + rbase;
                inv[mt][hf] = 1.f / (redsum[wid * 64 + idx] +
                                     redsum[(wid ^ 1) * 64 + idx]);
            }
#pragma unroll
        for (int mt = 0; mt < 4; mt++)
#pragma unroll
            for (int nt = 0; nt < 4; nt++) {
                acc[mt][nt][0] *= inv[mt][0]; acc[mt][nt][1] *= inv[mt][0];
                acc[mt][nt][2] *= inv[mt][1]; acc[mt][nt][3] *= inv[mt][1];
            }
    }

#pragma unroll
    for (int mt = 0; mt < 4; mt++) {
        const int row0 = bm + wm + mt * 16 + (lane >> 2);
        const int row1 = row0 + 8;
        bool sub0 = false, sub1 = false;
        if (dokhm) {
            sub0 = (row0 < cnt) && !g_km[g_kidx[row0]];
            sub1 = (row1 < cnt) && !g_km[g_kidx[row1]];
            // rows in compact list are unmasked by construction; sub stays false.
            (void)sub0; (void)sub1;
        }
#pragma unroll
        for (int nt = 0; nt < 4; nt++) {
            const int col = bn + wn + nt * 8 + cl;
            float2 o0{acc[mt][nt][0], acc[mt][nt][1]};
            float2 o1{acc[mt][nt][2], acc[mt][nt][3]};
            if (scatter) {
                if (row0 < cnt) *(float2*)&C[(size_t)g_qidx[row0] * Ee + col] = o0;
                if (row1 < cnt) *(float2*)&C[(size_t)g_qidx[row1] * Ee + col] = o1;
            } else {
                if (row0 < cnt) *(float2*)&C[(size_t)row0 * Ee + col] = o0;
                if (row1 < cnt) *(float2*)&C[(size_t)row1 * Ee + col] = o1;
            }
        }
    }
}

// batched QKV projection GEMM: z = 0 Q(softmax), 1 K(softmax), 2 V(plain)
__global__ __launch_bounds__(256, 2) void tgemm_qkv(
    const float* __restrict__ bq, const float* __restrict__ bk,
    const float* __restrict__ bv)
{
    __shared__ __align__(128) char smraw[49152];
    const int z = blockIdx.z;
    const int cnt = (z == 0) ? g_qoff[4] : g_koff[4];
    const int bm = blockIdx.y * 128;
    if (bm >= cnt) return;
    const int bn = blockIdx.x * 128;
    const __nv_bfloat16* Ahi = (z == 0) ? g_Qhi : (z == 1) ? g_Khi : g_Vhi;
    const __nv_bfloat16* Alo = (z == 0) ? g_Qlo : (z == 1) ? g_Klo : g_Vlo;
    const __nv_bfloat16* Bhi = (z == 0) ? g_Wqhi : (z == 1) ? g_Wkhi : g_Wvhi;
    const __nv_bfloat16* Blo = (z == 0) ? g_Wqlo : (z == 1) ? g_Wklo : g_Wvlo;
    const float* bias = (z == 0) ? bq : (z == 1) ? bk : bv;
    float* C = (z == 0) ? g_QH : (z == 1) ? g_KH : g_VH;
    gemm_body(Ahi, Alo, Bhi, Blo, bias, C, cnt, bm, bn,
              /*dosm=*/z != 2, /*dokhm=*/false, /*scatter=*/false, smraw);
}

// final output-projection GEMM (scatter via qidx)
__global__ __launch_bounds__(256, 2) void tgemm_fin(const float* __restrict__ bias,
                                                    float* __restrict__ Cext)
{
    __shared__ __align__(128) char smraw[49152];
    const int cnt = g_qoff[4];
    const int bm = blockIdx.y * 128;
    if (bm >= cnt) return;
    gemm_body(g_Qhi, g_Qlo, g_Wqhi, g_Wqlo, bias, Cext, cnt, bm,
              blockIdx.x * 128, false, false, /*scatter=*/true, smraw);
}

// =====================================================================
// init ctx/kcum with analytic masked-row corrections
// =====================================================================
__global__ void init_ctx(const float* __restrict__ bv)
{
    const int bh = blockIdx.x;
    const int b = bh >> 4, h = bh & 15;
    const float nm = (float)(Ss - (g_koff[b + 1] - g_koff[b]));
    for (int i = threadIdx.x; i < Dd * Dd; i += 256) {
        const int d = i >> 6, e = i & 63;
        g_ctx[bh * Dd * Dd + i] = nm * g_khm[h * Dd + d] * bv[h * Dd + e];
    }
    if (threadIdx.x < 64)
        g_kcum[bh * Dd + threadIdx.x] = nm * g_khm[h * Dd + threadIdx.x];
}

// =====================================================================
// context over compacted per-batch segment; folds kcum.
// =====================================================================
__global__ __launch_bounds__(256) void context_kernel()
{
    const int bh = blockIdx.y;
    const int b = bh >> 4, h = bh & 15;
    const int base = g_koff[b];
    const int cntb = g_koff[b + 1] - base;
    const int s0 = blockIdx.x * 256;
    if (s0 >= cntb) return;

    __shared__ __align__(16) float kh[3][16][64];
    __shared__ __align__(16) float vh[3][16][64];

    const int tid  = threadIdx.x;
    const int dB   = (tid >> 4) * 4;
    const int eB   = (tid & 15) * 4;
    const int lrow = tid >> 4;
    const int lseg = tid & 15;
    const uint32_t kB = smem_u32(&kh[0][0][0]);
    const uint32_t vB = smem_u32(&vh[0][0][0]);

    auto issue = [&](int t, int st) {
        const int row = s0 + t * 16 + lrow;
        const uint32_t sz = (row < cntb) ? 16u : 0u;
        const int rc = (row < cntb) ? row : 0;
        const size_t g = ((size_t)(base + rc)) * Ee + h * Dd + lseg * 4;
        CP_ASYNC16P(kB + st * 4096 + lrow * 256 + lseg * 16, g_KH + g, sz);
        CP_ASYNC16P(vB + st * 4096 + lrow * 256 + lseg * 16, g_VH + g, sz);
        CP_COMMIT();
    };

    float acc[4][4];
#pragma unroll
    for (int i = 0; i < 4; i++)
#pragma unroll
        for (int l = 0; l < 4; l++) acc[i][l] = 0.f;
    float kcp[4] = {0.f, 0.f, 0.f, 0.f};

    issue(0, 0);
    issue(1, 1);
#pragma unroll 1
    for (int t = 0; t < 16; t++) {
        if (t < 15) { CP_WAIT(1); } else { CP_WAIT(0); }
        __syncthreads();
        const int st = t % 3;
#pragma unroll
        for (int j = 0; j < 16; j++) {
            const float4 kv = *(const float4*)&kh[st][j][dB];
            const float4 vv = *(const float4*)&vh[st][j][eB];
            kcp[0] += kv.x; kcp[1] += kv.y; kcp[2] += kv.z; kcp[3] += kv.w;
            acc[0][0] += kv.x * vv.x; acc[0][1] += kv.x * vv.y;
            acc[0][2] += kv.x * vv.z; acc[0][3] += kv.x * vv.w;
            acc[1][0] += kv.y * vv.x; acc[1][1] += kv.y * vv.y;
            acc[1][2] += kv.y * vv.z; acc[1][3] += kv.y * vv.w;
            acc[2][0] += kv.z * vv.x; acc[2][1] += kv.z * vv.y;
            acc[2][2] += kv.z * vv.z; acc[2][3] += kv.z * vv.w;
            acc[3][0] += kv.w * vv.x; acc[3][1] += kv.w * vv.y;
            acc[3][2] += kv.w * vv.z; acc[3][3] += kv.w * vv.w;
        }
        if (t + 2 < 16) issue(t + 2, (t + 2) % 3);
    }

    float* ctx = g_ctx + (size_t)bh * Dd * Dd;
#pragma unroll
    for (int i = 0; i < 4; i++)
#pragma unroll
        for (int l = 0; l < 4; l++)
            atomicAdd(&ctx[(dB + i) * Dd + eB + l], acc[i][l]);
    if ((tid & 15) == 0) {
#pragma unroll
        for (int i = 0; i < 4; i++)
            atomicAdd(&g_kcum[bh * Dd + dB + i], kcp[i]);
    }
}

// =====================================================================
// combine over compacted q rows; emits hi/lo bf16 into g_Qhi/g_Qlo.
// =====================================================================
__global__ __launch_bounds__(256) void combine_kernel()
{
    const int bh = blockIdx.y;
    const int b = bh >> 4, h = bh & 15;
    const int base = g_qoff[b];
    const int cntb = g_qoff[b + 1] - base;
    const int s0 = blockIdx.x * 128;
    if (s0 >= cntb) return;

    __shared__ float ctx[64][64];
    __shared__ float kc[64];
    for (int i = threadIdx.x; i < Dd * Dd; i += 256)
        ((float*)ctx)[i] = g_ctx[(size_t)bh * Dd * Dd + i];
    if (threadIdx.x < 64) kc[threadIdx.x] = g_kcum[bh * Dd + threadIdx.x];
    __syncthreads();

    const int warp = threadIdx.x >> 5, lane = threadIdx.x & 31;
    const int lim = (s0 + 128 < cntb) ? (s0 + 128) : cntb;
    for (int s = s0 + warp; s < lim; s += 8) {
        const size_t gi = ((size_t)(base + s)) * Ee + h * Dd;
        const float* p = g_QH + gi;
        const float q0 = p[lane], q1 = p[lane + 32];
        float dot = q0 * kc[lane] + q1 * kc[lane + 32];
#pragma unroll
        for (int o = 16; o; o >>= 1) dot += __shfl_xor_sync(0xffffffffu, dot, o);
        const float a = 1.f / dot;
        float o0 = 0.f, o1 = 0.f;
#pragma unroll
        for (int d = 0; d < 32; d++) {
            const float qd = __shfl_sync(0xffffffffu, q0, d);
            o0 += qd * ctx[d][lane];
            o1 += qd * ctx[d][lane + 32];
        }
#pragma unroll
        for (int d = 0; d < 32; d++) {
            const float qd = __shfl_sync(0xffffffffu, q1, d);
            o0 += qd * ctx[d + 32][lane];
            o1 += qd * ctx[d + 32][lane + 32];
        }
        const float r0 = o0 * a + q0;
        const float r1 = o1 * a + q1;
        __nv_bfloat16 h0 = __float2bfloat16(r0);
        __nv_bfloat16 h1 = __float2bfloat16(r1);
        g_Qhi[gi + lane]      = h0;
        g_Qhi[gi + lane + 32] = h1;
        g_Qlo[gi + lane]      = __float2bfloat16(r0 - __bfloat162float(h0));
        g_Qlo[gi + lane + 32] = __float2bfloat16(r1 - __bfloat162float(h1));
    }
}

// zero masked output rows
__global__ __launch_bounds__(256) void zero_out_kernel(float* __restrict__ out)
{
    const int row = blockIdx.x * 8 + (threadIdx.x >> 5);
    if (g_qm[row]) return;
    const int lane = threadIdx.x & 31;
    const float4 z{0.f, 0.f, 0.f, 0.f};
    float4* o = (float4*)(out + (size_t)row * Ee);
#pragma unroll
    for (int j = 0; j < 8; j++) o[lane + j * 32] = z;
}

// =====================================================================
extern "C" void kernel_launch(void* const* d_in, const int* in_sizes, int n_in,
                              void* d_out, int out_size)
{
    const float* q  = (const float*)d_in[0];
    const float* k  = (const float*)d_in[1];
    const float* v  = (const float*)d_in[2];
    const unsigned char* qm_raw = (const unsigned char*)d_in[3];
    const unsigned char* km_raw = (const unsigned char*)d_in[4];
    const float* Wq = (const float*)d_in[5];
    const float* bq = (const float*)d_in[6];
    const float* Wk = (const float*)d_in[7];
    const float* bk = (const float*)d_in[8];
    const float* Wv = (const float*)d_in[9];
    const float* bv = (const float*)d_in[10];
    const float* Wp = (const float*)d_in[11];
    const float* bp = (const float*)d_in[12];
    float* out = (float*)d_out;

    // 0) masks -> compaction lists; exact masked-k vector (parallel)
    norm_mask_kernel<true ><<<1, 256>>>(qm_raw, Mtot);
    norm_mask_kernel<false><<<1, 256>>>(km_raw, Mtot);
    scan_kernel<<<1, 256>>>();
    khmask1_kernel<<<128, 256>>>(Wk, bk);
    khmask2_kernel<<<1, 32>>>();

    // 1) batched conversions + batched QKV GEMM (fused softmax epilogues)
    conv_a3<<<dim3(2048, 3), 256>>>(q, k, v);
    conv_w3<<<dim3(128, 3), 256>>>(Wq, Wk, Wv);
    tgemm_qkv<<<dim3(8, 128, 3), 256>>>(bq, bk, bv);

    // 2) linear-attention core with analytic masked-row corrections
    init_ctx<<<Bb * Hh, 256>>>(bv);
    context_kernel<<<dim3(16, Bb * Hh), 256>>>();
    combine_kernel<<<dim3(32, Bb * Hh), 256>>>();

    // 3) output projection: zero masked rows, scatter unmasked rows
    conv_w1<<<128, 256>>>(Wp);
    zero_out_kernel<<<2048, 256>>>(out);
    tgemm_fin<<<dim3(8, 128), 256>>>(bp, out);
}

// round 10
// speedup vs baseline: 3.1672x; 1.0326x over previous
#include <cuda_runtime.h>
#include <cuda_bf16.h>
#include <math.h>
#include <stdint.h>

// ---------------- problem constants ----------------
constexpr int Bb = 4;
constexpr int Ss = 4096;
constexpr int Ee = 1024;
constexpr int Hh = 16;
constexpr int Dd = 64;
constexpr int Mtot = Bb * Ss;

// ---------------- scratch (device globals; device-code refs only) ----------------
__device__ __align__(16) float g_QH[(size_t)Mtot * Ee];
__device__ __align__(16) float g_KH[(size_t)Mtot * Ee];
__device__ __align__(16) float g_VH[(size_t)Mtot * Ee];
__device__ __align__(16) float g_ctx[Bb * Hh * Dd * Dd];
__device__ __align__(16) float g_kcum[Bb * Hh * Dd];
__device__ __align__(16) float g_mvec[Ee];
__device__ unsigned char g_qm[Mtot];
__device__ unsigned char g_km[Mtot];
__device__ int g_qidx[Mtot];
__device__ int g_kidx[Mtot];
__device__ int g_qoff[5];
__device__ int g_koff[5];
// per-input split-bf16 operand buffers (compact rows)
__device__ __align__(16) __nv_bfloat16 g_Qhi[(size_t)Mtot * Ee];
__device__ __align__(16) __nv_bfloat16 g_Qlo[(size_t)Mtot * Ee];
__device__ __align__(16) __nv_bfloat16 g_Khi[(size_t)Mtot * Ee];
__device__ __align__(16) __nv_bfloat16 g_Klo[(size_t)Mtot * Ee];
__device__ __align__(16) __nv_bfloat16 g_Vhi[(size_t)Mtot * Ee];
__device__ __align__(16) __nv_bfloat16 g_Vlo[(size_t)Mtot * Ee];
__device__ __align__(16) __nv_bfloat16 g_Wqhi[(size_t)Ee * Ee];
__device__ __align__(16) __nv_bfloat16 g_Wqlo[(size_t)Ee * Ee];
__device__ __align__(16) __nv_bfloat16 g_Wkhi[(size_t)Ee * Ee];
__device__ __align__(16) __nv_bfloat16 g_Wklo[(size_t)Ee * Ee];
__device__ __align__(16) __nv_bfloat16 g_Wvhi[(size_t)Ee * Ee];
__device__ __align__(16) __nv_bfloat16 g_Wvlo[(size_t)Ee * Ee];
__device__ __align__(16) __nv_bfloat16 g_Wphi[(size_t)Ee * Ee];
__device__ __align__(16) __nv_bfloat16 g_Wplo[(size_t)Ee * Ee];

// =====================================================================
// helpers
// =====================================================================
__device__ __forceinline__ uint32_t smem_u32(const void* p) {
    uint32_t a;
    asm("{ .reg .u64 t; cvta.to.shared.u64 t, %1; cvt.u32.u64 %0, t; }" : "=r"(a) : "l"(p));
    return a;
}
__device__ __forceinline__ uint32_t sw64(uint32_t off) { return off ^ ((off >> 3) & 0x30); }

#define CP_ASYNC16(dst, src) \
    asm volatile("cp.async.cg.shared.global [%0], [%1], 16;" :: "r"(dst), "l"(src))
#define CP_ASYNC16P(dst, src, sz) \
    asm volatile("cp.async.cg.shared.global [%0], [%1], 16, %2;" :: "r"(dst), "l"(src), "r"(sz))
#define CP_COMMIT() asm volatile("cp.async.commit_group;" ::: "memory")
#define CP_WAIT(N)  asm volatile("cp.async.wait_group %0;" :: "n"(N) : "memory")

#define LDSM4(r, addr)                                                            \
    asm volatile("ldmatrix.sync.aligned.m8n8.x4.shared.b16 {%0,%1,%2,%3}, [%4];"  \
        : "=r"((r)[0]), "=r"((r)[1]), "=r"((r)[2]), "=r"((r)[3]) : "r"(addr))

#define MMA_BF16(d, a, b0, b1)                                                    \
    asm volatile("mma.sync.aligned.m16n8k16.row.col.f32.bf16.bf16.f32 "           \
        "{%0,%1,%2,%3}, {%4,%5,%6,%7}, {%8,%9}, {%0,%1,%2,%3};"                   \
        : "+f"((d)[0]), "+f"((d)[1]), "+f"((d)[2]), "+f"((d)[3])                  \
        : "r"((a)[0]), "r"((a)[1]), "r"((a)[2]), "r"((a)[3]), "r"(b0), "r"(b1))

__device__ __forceinline__ void split4(float4 x, uint2& hv, uint2& lv) {
    __nv_bfloat16 h0 = __float2bfloat16(x.x), h1 = __float2bfloat16(x.y);
    __nv_bfloat16 h2 = __float2bfloat16(x.z), h3 = __float2bfloat16(x.w);
    __nv_bfloat16 l0 = __float2bfloat16(x.x - __bfloat162float(h0));
    __nv_bfloat16 l1 = __float2bfloat16(x.y - __bfloat162float(h1));
    __nv_bfloat16 l2 = __float2bfloat16(x.z - __bfloat162float(h2));
    __nv_bfloat16 l3 = __float2bfloat16(x.w - __bfloat162float(h3));
    __nv_bfloat162 a{h0, h1}, b{h2, h3}, c{l0, l1}, d{l2, l3};
    hv.x = *(uint32_t*)&a; hv.y = *(uint32_t*)&b;
    lv.x = *(uint32_t*)&c; lv.y = *(uint32_t*)&d;
}

// =====================================================================
// Mask normalization, both masks in one launch (blockIdx.y selects).
// =====================================================================
__global__ void norm_mask2(const unsigned char* __restrict__ qsrc,
                           const unsigned char* __restrict__ ksrc, int n)
{
    const unsigned char* src = blockIdx.y ? ksrc : qsrc;
    unsigned char* dst = blockIdx.y ? g_km : g_qm;
    __shared__ int vote_u8, any_nz;
    if (threadIdx.x == 0) { vote_u8 = 0; any_nz = 0; }
    __syncthreads();
    const unsigned int* w = (const unsigned int*)src;
    const int nw = n >> 2;
    int l_u8 = 0, l_nz = 0;
    for (int i = threadIdx.x; i < nw; i += blockDim.x) {
        unsigned int vv = w[i];
        if (vv != 0u) l_nz = 1;
        if (vv != 0u && vv != 1u && vv != 0x3F800000u) l_u8 = 1;
    }
    if (l_u8) vote_u8 = 1;
    if (l_nz) any_nz = 1;
    __syncthreads();
    if (!any_nz) {
        for (int i = threadIdx.x; i < n; i += blockDim.x) dst[i] = 0;
    } else if (vote_u8) {
        for (int i = threadIdx.x; i < n; i += blockDim.x) dst[i] = src[i] ? 1 : 0;
    } else {
        for (int i = threadIdx.x; i < n; i += blockDim.x) dst[i] = w[i] ? 1 : 0;
    }
}

// =====================================================================
// Deterministic compaction scan
// =====================================================================
__global__ void scan_kernel()
{
    __shared__ int qc[256], kc[256], qs[257], ks[257];
    const int t = threadIdx.x;
    int nq = 0, nk = 0;
#pragma unroll 4
    for (int i = 0; i < 64; i++) {
        nq += g_qm[t * 64 + i] ? 1 : 0;
        nk += g_km[t * 64 + i] ? 1 : 0;
    }
    qc[t] = nq; kc[t] = nk;
    __syncthreads();
    if (t == 0) {
        int aq = 0, ak = 0;
        for (int i = 0; i < 256; i++) { qs[i] = aq; ks[i] = ak; aq += qc[i]; ak += kc[i]; }
        qs[256] = aq; ks[256] = ak;
        for (int b = 0; b <= 4; b++) { g_qoff[b] = qs[b * 64]; g_koff[b] = ks[b * 64]; }
    }
    __syncthreads();
    int pq = qs[t], pk = ks[t];
    for (int i = 0; i < 64; i++) {
        const int r = t * 64 + i;
        if (g_qm[r]) g_qidx[pq++] = r;
        if (g_km[r]) g_kidx[pk++] = r;
    }
}

// =====================================================================
// All conversions in one launch. grid (2048, 4):
//   z=0 q-list<-q, z=1 k-list<-k, z=2 k-list<-v (compact gather + split)
//   z=3: bx<512: W matrices (bx>>7 selects Wq/Wk/Wv/Wp)
// =====================================================================
__global__ __launch_bounds__(256) void conv_all(
    const float* __restrict__ q, const float* __restrict__ k,
    const float* __restrict__ v,
    const float* __restrict__ Wq, const float* __restrict__ Wk,
    const float* __restrict__ Wv, const float* __restrict__ Wp)
{
    const int z = blockIdx.y;
    if (z < 3) {
        const int cnt = (z == 0) ? g_qoff[4] : g_koff[4];
        const int ci = blockIdx.x * 8 + (threadIdx.x >> 5);
        if (ci >= cnt) return;
        const int orig = (z == 0) ? g_qidx[ci] : g_kidx[ci];
        const float* __restrict__ src = (z == 0) ? q : (z == 1) ? k : v;
        __nv_bfloat16* hi = (z == 0) ? g_Qhi : (z == 1) ? g_Khi : g_Vhi;
        __nv_bfloat16* lo = (z == 0) ? g_Qlo : (z == 1) ? g_Klo : g_Vlo;
        const int lane = threadIdx.x & 31;
        const float4* s = (const float4*)(src + (size_t)orig * Ee);
        hi += (size_t)ci * Ee;
        lo += (size_t)ci * Ee;
        float4 xs[8];
#pragma unroll
        for (int j = 0; j < 8; j++) xs[j] = s[lane + j * 32];
#pragma unroll
        for (int j = 0; j < 8; j++) {
            uint2 hv, lv;
            split4(xs[j], hv, lv);
            *(uint2*)&hi[(lane + j * 32) * 4] = hv;
            *(uint2*)&lo[(lane + j * 32) * 4] = lv;
        }
    } else {
        const int bx = blockIdx.x;
        if (bx >= 512) return;
        const int wsel = bx >> 7;
        const float* __restrict__ W =
            (wsel == 0) ? Wq : (wsel == 1) ? Wk : (wsel == 2) ? Wv : Wp;
        __nv_bfloat16* hi =
            (wsel == 0) ? g_Wqhi : (wsel == 1) ? g_Wkhi : (wsel == 2) ? g_Wvhi : g_Wphi;
        __nv_bfloat16* lo =
            (wsel == 0) ? g_Wqlo : (wsel == 1) ? g_Wklo : (wsel == 2) ? g_Wvlo : g_Wplo;
        const size_t base = (size_t)(bx & 127) * 256 + threadIdx.x;
        constexpr size_t stride = 128u * 256u;
        float4 xs[8];
#pragma unroll
        for (int it = 0; it < 8; it++)
            xs[it] = ((const float4*)W)[base + (size_t)it * stride];
#pragma unroll
        for (int it = 0; it < 8; it++) {
            const size_t i4 = base + (size_t)it * stride;
            uint2 hv, lv;
            split4(xs[it], hv, lv);
            *(uint2*)&hi[i4 * 4] = hv;
            *(uint2*)&lo[i4 * 4] = lv;
        }
    }
}

// =====================================================================
// khmask stage 1: parallel rowsums (warp per row, fixed lane-stride order)
// =====================================================================
__global__ __launch_bounds__(256) void khmask1_kernel(const float* __restrict__ Wk,
                                                      const float* __restrict__ bk)
{
    const int r = blockIdx.x * 8 + (threadIdx.x >> 5);
    const int lane = threadIdx.x & 31;
    float s = 0.f;
    for (int e = lane; e < Ee; e += 32) s += Wk[(size_t)r * Ee + e];
#pragma unroll
    for (int o = 16; o; o >>= 1) s += __shfl_xor_sync(0xffffffffu, s, o);
    if (lane == 0) g_mvec[r] = -1e9f * s + bk[r];
}

// =====================================================================
// GEMM mainloop+epilogue shared body (device inline).
// =====================================================================
__device__ __forceinline__ void gemm_body(
    const __nv_bfloat16* __restrict__ Ahi, const __nv_bfloat16* __restrict__ Alo,
    const __nv_bfloat16* __restrict__ Bhi, const __nv_bfloat16* __restrict__ Blo,
    const float* __restrict__ bias, float* __restrict__ C,
    int cnt, int bm, int bn, bool dosm, bool scatter, char* smraw)
{
    __nv_bfloat16* smA = (__nv_bfloat16*)smraw;            // 3 x 8KB
    __nv_bfloat16* smB = (__nv_bfloat16*)(smraw + 24576);  // 3 x 8KB

    const int tid  = threadIdx.x;
    const int lane = tid & 31;
    const int wid  = tid >> 5;
    const int wm   = (wid >> 2) * 64;
    const int wn   = (wid & 3) * 32;

    const uint32_t smA0 = smem_u32(smA);
    const uint32_t smB0 = smem_u32(smB);

    const int ldrow = tid >> 1;
    const int ldseg = (tid & 1) * 2;
    const uint32_t asz = (bm + ldrow < cnt) ? 16u : 0u;

    float acc[4][4][4];
#pragma unroll
    for (int mt = 0; mt < 4; mt++)
#pragma unroll
        for (int nt = 0; nt < 4; nt++)
#pragma unroll
            for (int i = 0; i < 4; i++) acc[mt][nt][i] = 0.f;

    auto issue = [&](int s, int st) {
        const int prod = s >> 5;
        const __nv_bfloat16* __restrict__ Ab = (prod == 2) ? Alo : Ahi;
        const __nv_bfloat16* __restrict__ Bb = (prod == 1) ? Blo : Bhi;
        const int ks = (s & 31) * 32;
#pragma unroll
        for (int i = 0; i < 2; i++) {
            const int seg = ldseg + i;
            const uint32_t so = sw64((uint32_t)(ldrow * 64 + seg * 16));
            CP_ASYNC16P(smA0 + st * 8192 + so,
                        Ab + (size_t)(bm + ldrow) * Ee + ks + seg * 8, asz);
            CP_ASYNC16(smB0 + st * 8192 + so,
                       Bb + (size_t)(bn + ldrow) * Ee + ks + seg * 8);
        }
        CP_COMMIT();
    };

    issue(0, 0);
    issue(1, 1);

    const int q = lane >> 3, r = lane & 7;

#pragma unroll 1
    for (int s = 0; s < 96; s++) {
        if (s < 95) { CP_WAIT(1); } else { CP_WAIT(0); }
        __syncthreads();
        const int st = s % 3;
        const uint32_t aB = smA0 + st * 8192;
        const uint32_t bB = smB0 + st * 8192;
#pragma unroll
        for (int kk = 0; kk < 32; kk += 16) {
            uint32_t afr[4][4], bfr[2][4];
#pragma unroll
            for (int mt = 0; mt < 4; mt++) {
                const int row = wm + mt * 16 + (q & 1) * 8 + r;
                LDSM4(afr[mt], aB + sw64((uint32_t)(row * 64 + kk * 2 + (q >> 1) * 16)));
            }
            {
                const int rowb = wn + q * 8 + r;
                LDSM4(bfr[0], bB + sw64((uint32_t)(rowb * 64 + kk * 2)));
                LDSM4(bfr[1], bB + sw64((uint32_t)(rowb * 64 + kk * 2 + 16)));
            }
#pragma unroll
            for (int mt = 0; mt < 4; mt++)
#pragma unroll
                for (int nt = 0; nt < 4; nt++)
                    MMA_BF16(acc[mt][nt], afr[mt], bfr[0][nt], bfr[1][nt]);
        }
        if (s + 2 < 96) issue(s + 2, (s + 2) % 3);
    }

    // ---- epilogue ----
    __syncthreads();

    const int cl = 2 * (lane & 3);
#pragma unroll
    for (int nt = 0; nt < 4; nt++) {
        const float2 bb = *(const float2*)&bias[bn + wn + nt * 8 + cl];
#pragma unroll
        for (int mt = 0; mt < 4; mt++) {
            acc[mt][nt][0] += bb.x; acc[mt][nt][1] += bb.y;
            acc[mt][nt][2] += bb.x; acc[mt][nt][3] += bb.y;
        }
    }

    if (dosm) {
        float* redmax = (float*)smA;
        float* redsum = redmax + 512;
        const int rbase = (lane >> 2);
        float inv[4][2];
#pragma unroll
        for (int mt = 0; mt < 4; mt++)
#pragma unroll
            for (int hf = 0; hf < 2; hf++) {
                float m = -3.4e38f;
#pragma unroll
                for (int nt = 0; nt < 4; nt++)
                    m = fmaxf(m, fmaxf(acc[mt][nt][2 * hf], acc[mt][nt][2 * hf + 1]));
                m = fmaxf(m, __shfl_xor_sync(0xffffffffu, m, 1));
                m = fmaxf(m, __shfl_xor_sync(0xffffffffu, m, 2));
                if ((lane & 3) == 0)
                    redmax[wid * 64 + mt * 16 + hf * 8 + rbase] = m;
            }
        __syncthreads();
#pragma unroll
        for (int mt = 0; mt < 4; mt++)
#pragma unroll
            for (int hf = 0; hf < 2; hf++) {
                const int idx = mt * 16 + hf * 8 + rbase;
                const float rm = fmaxf(redmax[wid * 64 + idx],
                                       redmax[(wid ^ 1) * 64 + idx]);
                float s = 0.f;
#pragma unroll
                for (int nt = 0; nt < 4; nt++) {
                    float a0 = __expf(acc[mt][nt][2 * hf]     - rm);
                    float a1 = __expf(acc[mt][nt][2 * hf + 1] - rm);
                    acc[mt][nt][2 * hf] = a0; acc[mt][nt][2 * hf + 1] = a1;
                    s += a0 + a1;
                }
                s += __shfl_xor_sync(0xffffffffu, s, 1);
                s += __shfl_xor_sync(0xffffffffu, s, 2);
                if ((lane & 3) == 0)
                    redsum[wid * 64 + idx] = s;
            }
        __syncthreads();
#pragma unroll
        for (int mt = 0; mt < 4; mt++)
#pragma unroll
            for (int hf = 0; hf < 2; hf++) {
                const int idx = mt * 16 + hf * 8 + rbase;
                inv[mt][hf] = 1.f / (redsum[wid * 64 + idx] +
                                     redsum[(wid ^ 1) * 64 + idx]);
            }
#pragma unroll
        for (int mt = 0; mt < 4; mt++)
#pragma unroll
            for (int nt = 0; nt < 4; nt++) {
                acc[mt][nt][0] *= inv[mt][0]; acc[mt][nt][1] *= inv[mt][0];
                acc[mt][nt][2] *= inv[mt][1]; acc[mt][nt][3] *= inv[mt][1];
            }
    }

#pragma unroll
    for (int mt = 0; mt < 4; mt++) {
        const int row0 = bm + wm + mt * 16 + (lane >> 2);
        const int row1 = row0 + 8;
#pragma unroll
        for (int nt = 0; nt < 4; nt++) {
            const int col = bn + wn + nt * 8 + cl;
            float2 o0{acc[mt][nt][0], acc[mt][nt][1]};
            float2 o1{acc[mt][nt][2], acc[mt][nt][3]};
            if (scatter) {
                if (row0 < cnt) *(float2*)&C[(size_t)g_qidx[row0] * Ee + col] = o0;
                if (row1 < cnt) *(float2*)&C[(size_t)g_qidx[row1] * Ee + col] = o1;
            } else {
                if (row0 < cnt) *(float2*)&C[(size_t)row0 * Ee + col] = o0;
                if (row1 < cnt) *(float2*)&C[(size_t)row1 * Ee + col] = o1;
            }
        }
    }
}

// batched QKV projection GEMM: z = 0 Q(softmax), 1 K(softmax), 2 V(plain)
__global__ __launch_bounds__(256, 2) void tgemm_qkv(
    const float* __restrict__ bq, const float* __restrict__ bk,
    const float* __restrict__ bv)
{
    __shared__ __align__(128) char smraw[49152];
    const int z = blockIdx.z;
    const int cnt = (z == 0) ? g_qoff[4] : g_koff[4];
    const int bm = blockIdx.y * 128;
    if (bm >= cnt) return;
    const int bn = blockIdx.x * 128;
    const __nv_bfloat16* Ahi = (z == 0) ? g_Qhi : (z == 1) ? g_Khi : g_Vhi;
    const __nv_bfloat16* Alo = (z == 0) ? g_Qlo : (z == 1) ? g_Klo : g_Vlo;
    const __nv_bfloat16* Bhi = (z == 0) ? g_Wqhi : (z == 1) ? g_Wkhi : g_Wvhi;
    const __nv_bfloat16* Blo = (z == 0) ? g_Wqlo : (z == 1) ? g_Wklo : g_Wvlo;
    const float* bias = (z == 0) ? bq : (z == 1) ? bk : bv;
    float* C = (z == 0) ? g_QH : (z == 1) ? g_KH : g_VH;
    gemm_body(Ahi, Alo, Bhi, Blo, bias, C, cnt, bm, bn,
              /*dosm=*/z != 2, /*scatter=*/false, smraw);
}

// final output-projection GEMM (scatter via qidx; uses Wp buffers)
__global__ __launch_bounds__(256, 2) void tgemm_fin(const float* __restrict__ bias,
                                                    float* __restrict__ Cext)
{
    __shared__ __align__(128) char smraw[49152];
    const int cnt = g_qoff[4];
    const int bm = blockIdx.y * 128;
    if (bm >= cnt) return;
    gemm_body(g_Qhi, g_Qlo, g_Wphi, g_Wplo, bias, Cext, cnt, bm,
              blockIdx.x * 128, false, /*scatter=*/true, smraw);
}

// =====================================================================
// init ctx/kcum with analytic masked-row corrections; computes the exact
// masked-row softmax vector locally from g_mvec (same serial formula).
// =====================================================================
__global__ void init_ctx(const float* __restrict__ bv)
{
    const int bh = blockIdx.x;
    const int b = bh >> 4, h = bh & 15;
    __shared__ float khm[Dd];
    if (threadIdx.x == 0) {
        float mx = -3.4e38f;
        for (int d = 0; d < Dd; d++) mx = fmaxf(mx, g_mvec[h * Dd + d]);
        float sm = 0.f;
        for (int d = 0; d < Dd; d++) sm += expf(g_mvec[h * Dd + d] - mx);
        const float inv = 1.f / sm;
        for (int d = 0; d < Dd; d++) khm[d] = expf(g_mvec[h * Dd + d] - mx) * inv;
    }
    __syncthreads();
    const float nm = (float)(Ss - (g_koff[b + 1] - g_koff[b]));
    for (int i = threadIdx.x; i < Dd * Dd; i += 256) {
        const int d = i >> 6, e = i & 63;
        g_ctx[bh * Dd * Dd + i] = nm * khm[d] * bv[h * Dd + e];
    }
    if (threadIdx.x < 64)
        g_kcum[bh * Dd + threadIdx.x] = nm * khm[threadIdx.x];
}

// =====================================================================
// context over compacted per-batch segment; folds kcum.
// =====================================================================
__global__ __launch_bounds__(256) void context_kernel()
{
    const int bh = blockIdx.y;
    const int b = bh >> 4, h = bh & 15;
    const int base = g_koff[b];
    const int cntb = g_koff[b + 1] - base;
    const int s0 = blockIdx.x * 256;
    if (s0 >= cntb) return;

    __shared__ __align__(16) float kh[3][16][64];
    __shared__ __align__(16) float vh[3][16][64];

    const int tid  = threadIdx.x;
    const int dB   = (tid >> 4) * 4;
    const int eB   = (tid & 15) * 4;
    const int lrow = tid >> 4;
    const int lseg = tid & 15;
    const uint32_t kB = smem_u32(&kh[0][0][0]);
    const uint32_t vB = smem_u32(&vh[0][0][0]);

    auto issue = [&](int t, int st) {
        const int row = s0 + t * 16 + lrow;
        const uint32_t sz = (row < cntb) ? 16u : 0u;
        const int rc = (row < cntb) ? row : 0;
        const size_t g = ((size_t)(base + rc)) * Ee + h * Dd + lseg * 4;
        CP_ASYNC16P(kB + st * 4096 + lrow * 256 + lseg * 16, g_KH + g, sz);
        CP_ASYNC16P(vB + st * 4096 + lrow * 256 + lseg * 16, g_VH + g, sz);
        CP_COMMIT();
    };

    float acc[4][4];
#pragma unroll
    for (int i = 0; i < 4; i++)
#pragma unroll
        for (int l = 0; l < 4; l++) acc[i][l] = 0.f;
    float kcp[4] = {0.f, 0.f, 0.f, 0.f};

    issue(0, 0);
    issue(1, 1);
#pragma unroll 1
    for (int t = 0; t < 16; t++) {
        if (t < 15) { CP_WAIT(1); } else { CP_WAIT(0); }
        __syncthreads();
        const int st = t % 3;
#pragma unroll
        for (int j = 0; j < 16; j++) {
            const float4 kv = *(const float4*)&kh[st][j][dB];
            const float4 vv = *(const float4*)&vh[st][j][eB];
            kcp[0] += kv.x; kcp[1] += kv.y; kcp[2] += kv.z; kcp[3] += kv.w;
            acc[0][0] += kv.x * vv.x; acc[0][1] += kv.x * vv.y;
            acc[0][2] += kv.x * vv.z; acc[0][3] += kv.x * vv.w;
            acc[1][0] += kv.y * vv.x; acc[1][1] += kv.y * vv.y;
            acc[1][2] += kv.y * vv.z; acc[1][3] += kv.y * vv.w;
            acc[2][0] += kv.z * vv.x; acc[2][1] += kv.z * vv.y;
            acc[2][2] += kv.z * vv.z; acc[2][3] += kv.z * vv.w;
            acc[3][0] += kv.w * vv.x; acc[3][1] += kv.w * vv.y;
            acc[3][2] += kv.w * vv.z; acc[3][3] += kv.w * vv.w;
        }
        if (t + 2 < 16) issue(t + 2, (t + 2) % 3);
    }

    float* ctx = g_ctx + (size_t)bh * Dd * Dd;
#pragma unroll
    for (int i = 0; i < 4; i++)
#pragma unroll
        for (int l = 0; l < 4; l++)
            atomicAdd(&ctx[(dB + i) * Dd + eB + l], acc[i][l]);
    if ((tid & 15) == 0) {
#pragma unroll
        for (int i = 0; i < 4; i++)
            atomicAdd(&g_kcum[bh * Dd + dB + i], kcp[i]);
    }
}

// =====================================================================
// combine over compacted q rows; emits hi/lo bf16 into g_Qhi/g_Qlo.
// =====================================================================
__global__ __launch_bounds__(256) void combine_kernel()
{
    const int bh = blockIdx.y;
    const int b = bh >> 4, h = bh & 15;
    const int base = g_qoff[b];
    const int cntb = g_qoff[b + 1] - base;
    const int s0 = blockIdx.x * 128;
    if (s0 >= cntb) return;

    __shared__ float ctx[64][64];
    __shared__ float kc[64];
    for (int i = threadIdx.x; i < Dd * Dd; i += 256)
        ((float*)ctx)[i] = g_ctx[(size_t)bh * Dd * Dd + i];
    if (threadIdx.x < 64) kc[threadIdx.x] = g_kcum[bh * Dd + threadIdx.x];
    __syncthreads();

    const int warp = threadIdx.x >> 5, lane = threadIdx.x & 31;
    const int lim = (s0 + 128 < cntb) ? (s0 + 128) : cntb;
    for (int s = s0 + warp; s < lim; s += 8) {
        const size_t gi = ((size_t)(base + s)) * Ee + h * Dd;
        const float* p = g_QH + gi;
        const float q0 = p[lane], q1 = p[lane + 32];
        float dot = q0 * kc[lane] + q1 * kc[lane + 32];
#pragma unroll
        for (int o = 16; o; o >>= 1) dot += __shfl_xor_sync(0xffffffffu, dot, o);
        const float a = 1.f / dot;
        float o0 = 0.f, o1 = 0.f;
#pragma unroll
        for (int d = 0; d < 32; d++) {
            const float qd = __shfl_sync(0xffffffffu, q0, d);
            o0 += qd * ctx[d][lane];
            o1 += qd * ctx[d][lane + 32];
        }
#pragma unroll
        for (int d = 0; d < 32; d++) {
            const float qd = __shfl_sync(0xffffffffu, q1, d);
            o0 += qd * ctx[d + 32][lane];
            o1 += qd * ctx[d + 32][lane + 32];
        }
        const float r0 = o0 * a + q0;
        const float r1 = o1 * a + q1;
        __nv_bfloat16 h0 = __float2bfloat16(r0);
        __nv_bfloat16 h1 = __float2bfloat16(r1);
        g_Qhi[gi + lane]      = h0;
        g_Qhi[gi + lane + 32] = h1;
        g_Qlo[gi + lane]      = __float2bfloat16(r0 - __bfloat162float(h0));
        g_Qlo[gi + lane + 32] = __float2bfloat16(r1 - __bfloat162float(h1));
    }
}

// zero masked output rows
__global__ __launch_bounds__(256) void zero_out_kernel(float* __restrict__ out)
{
    const int row = blockIdx.x * 8 + (threadIdx.x >> 5);
    if (g_qm[row]) return;
    const int lane = threadIdx.x & 31;
    const float4 z{0.f, 0.f, 0.f, 0.f};
    float4* o = (float4*)(out + (size_t)row * Ee);
#pragma unroll
    for (int j = 0; j < 8; j++) o[lane + j * 32] = z;
}

// =====================================================================
extern "C" void kernel_launch(void* const* d_in, const int* in_sizes, int n_in,
                              void* d_out, int out_size)
{
    const float* q  = (const float*)d_in[0];
    const float* k  = (const float*)d_in[1];
    const float* v  = (const float*)d_in[2];
    const unsigned char* qm_raw = (const unsigned char*)d_in[3];
    const unsigned char* km_raw = (const unsigned char*)d_in[4];
    const float* Wq = (const float*)d_in[5];
    const float* bq = (const float*)d_in[6];
    const float* Wk = (const float*)d_in[7];
    const float* bk = (const float*)d_in[8];
    const float* Wv = (const float*)d_in[9];
    const float* bv = (const float*)d_in[10];
    const float* Wp = (const float*)d_in[11];
    const float* bp = (const float*)d_in[12];
    float* out = (float*)d_out;

    // 1-2) masks + compaction lists
    norm_mask2<<<dim3(1, 2), 256>>>(qm_raw, km_raw, Mtot);
    scan_kernel<<<1, 256>>>();

    // 3) all conversions (q/k/v gathers + Wq/Wk/Wv/Wp splits) in one launch
    conv_all<<<dim3(2048, 4), 256>>>(q, k, v, Wq, Wk, Wv, Wp);

    // 4) batched QKV GEMM (fused softmax epilogues)  <-- profiled launch
    tgemm_qkv<<<dim3(8, 128, 3), 256>>>(bq, bk, bv);

    // 5-7) masked-row analytics + output zeroing
    khmask1_kernel<<<128, 256>>>(Wk, bk);
    zero_out_kernel<<<2048, 256>>>(out);
    init_ctx<<<Bb * Hh, 256>>>(bv);

    // 8-9) linear-attention core
    context_kernel<<<dim3(16, Bb * Hh), 256>>>();
    combine_kernel<<<dim3(32, Bb * Hh), 256>>>();

    // 10) output projection (scatter unmasked rows)
    tgemm_fin<<<dim3(8, 128), 256>>>(bp, out);
}